// round 4
// baseline (speedup 1.0000x reference)
#include <cuda_runtime.h>
#include <math.h>

// Problem constants
#define BB 32
#define LL 64
#define EE 512
#define DH 1024
#define G4 4096
#define VV 32000

typedef unsigned long long ull;

// ---------------- scratch (device globals; no allocation allowed) ----------
__device__ float g_Xenc[LL * BB * G4];      // embed@enc_wx + enc_b  (33.5 MB)
__device__ float g_enc_outs[BB * LL * DH];  // encoder hidden states  (8.4 MB)
__device__ float g_part[8 * BB * G4];       // split-K partials       (4.2 MB)
__device__ float g_h[BB * DH];
__device__ float g_c[BB * DH];
__device__ float g_e[BB * DH];
__device__ float g_ctx[BB * DH];
__device__ float g_inp[BB * DH];
__device__ int   g_tok[BB];

// ---------------- f32x2 helpers (sm_103a packed FMA) -----------------------
__device__ __forceinline__ ull pk2(float w) {
    ull r; asm("mov.b64 %0, {%1, %1};" : "=l"(r) : "f"(w)); return r;
}
__device__ __forceinline__ void fma2(ull& d, ull a, ull b) {
    asm("fma.rn.f32x2 %0, %1, %2, %0;" : "+l"(d) : "l"(a), "l"(b));
}
__device__ __forceinline__ float2 upk(ull v) {
    float2 f; asm("mov.b64 {%0, %1}, %2;" : "=f"(f.x), "=f"(f.y) : "l"(v)); return f;
}
__device__ __forceinline__ float sigm(float x) { return 1.0f / (1.0f + expf(-x)); }

// ---------------- init: zero h/c (+ optional tok=127) ----------------------
__global__ void k_init(int settok) {
    int idx = blockIdx.x * blockDim.x + threadIdx.x;
    if (idx < BB * DH) { g_h[idx] = 0.f; g_c[idx] = 0.f; }
    if (settok && idx < BB) g_tok[idx] = 127;
}

// ---------------- one-time: Xenc[t] = embed(x[:,t]) @ enc_wx + enc_b -------
// grid (32, 1, 64), block 256.  NTILE=128 cols, 32 rows, K=512.
__global__ __launch_bounds__(256) void k_enc_pre(
    const int* __restrict__ x, const float* __restrict__ emb,
    const float* __restrict__ wx, const float* __restrict__ bias)
{
    __shared__ __align__(16) float As[32][34];
    int tid = threadIdx.x;
    int t = blockIdx.z;
    int tx = tid & 63, ty = tid >> 6;
    int c0 = blockIdx.x * 128 + tx;           // second col = c0 + 64
    int lb = tid >> 3, lk = (tid & 7) * 4;
    int tok = x[lb * LL + t];
    const float* arow = emb + (size_t)tok * EE;

    ull acc0[4] = {0, 0, 0, 0}, acc1[4] = {0, 0, 0, 0};
    for (int kc = 0; kc < EE; kc += 32) {
        __syncthreads();
        float4 v = *(const float4*)(arow + kc + lk);
        As[lk + 0][lb] = v.x; As[lk + 1][lb] = v.y;
        As[lk + 2][lb] = v.z; As[lk + 3][lb] = v.w;
        __syncthreads();
#pragma unroll 8
        for (int kk = 0; kk < 32; kk++) {
            const float* wrow = wx + (size_t)(kc + kk) * G4 + c0;
            ull w0 = pk2(wrow[0]);
            ull w1 = pk2(wrow[64]);
            const ull* ar = (const ull*)&As[kk][ty * 8];
#pragma unroll
            for (int r = 0; r < 4; r++) {
                ull a = ar[r];
                fma2(acc0[r], a, w0);
                fma2(acc1[r], a, w1);
            }
        }
    }
    float b0 = bias[c0], b1 = bias[c0 + 64];
    float* outt = g_Xenc + (size_t)t * BB * G4;
#pragma unroll
    for (int r = 0; r < 4; r++) {
        float2 v0 = upk(acc0[r]); float2 v1 = upk(acc1[r]);
        int row = ty * 8 + 2 * r;
        outt[row * G4 + c0]            = v0.x + b0;
        outt[(row + 1) * G4 + c0]      = v0.y + b0;
        outt[row * G4 + c0 + 64]       = v1.x + b1;
        outt[(row + 1) * G4 + c0 + 64] = v1.y + b1;
    }
}

// ---------------- generic split-K partial GEMM, M=32 -----------------------
// amode: 0 = A=g_h ; 1 = A=cat(g_e, g_ctx) ; 2 = A=cat(g_inp, g_h)
// grid (N/NTILE, 8).  Partial s written to g_part[s][b][0..Nout).
template <int NTILE>
__global__ __launch_bounds__(256) void k_gemm32(
    int amode, const float* __restrict__ W1, const float* __restrict__ W2,
    int Wsplit, int ldW, int KC, int Nout)
{
    constexpr int TXN = NTILE / 2;       // threads in col dim (2 cols/thread)
    constexpr int RP2 = TXN / 16;        // f32x2 row-pairs per thread
    __shared__ __align__(16) float As[32][34];
    int tid = threadIdx.x;
    int tx = tid % TXN, ty = tid / TXN;
    int c0 = blockIdx.x * NTILE + tx;
    int k0 = blockIdx.y * KC;

    const float* A1; const float* A2; int Asplit;
    if (amode == 0)      { A1 = g_h;   A2 = g_h;   Asplit = 1 << 30; }
    else if (amode == 1) { A1 = g_e;   A2 = g_ctx; Asplit = DH; }
    else                 { A1 = g_inp; A2 = g_h;   Asplit = DH; }
    const float* Ab = (k0 < Asplit) ? (A1 + k0) : (A2 + (k0 - Asplit));
    const float* Wb = (k0 < Wsplit) ? (W1 + (size_t)k0 * ldW)
                                    : (W2 + (size_t)(k0 - Wsplit) * ldW);
    int lb = tid >> 3, lk = (tid & 7) * 4;

    ull acc0[RP2], acc1[RP2];
#pragma unroll
    for (int r = 0; r < RP2; r++) { acc0[r] = 0; acc1[r] = 0; }

    for (int kc = 0; kc < KC; kc += 32) {
        __syncthreads();
        float4 v = *(const float4*)(Ab + lb * DH + kc + lk);
        As[lk + 0][lb] = v.x; As[lk + 1][lb] = v.y;
        As[lk + 2][lb] = v.z; As[lk + 3][lb] = v.w;
        __syncthreads();
#pragma unroll 8
        for (int kk = 0; kk < 32; kk++) {
            const float* wrow = Wb + (size_t)(kc + kk) * ldW + c0;
            ull w0 = pk2(wrow[0]);
            ull w1 = pk2(wrow[TXN]);
            const ull* ar = (const ull*)&As[kk][ty * RP2 * 2];
#pragma unroll
            for (int r = 0; r < RP2; r++) {
                ull a = ar[r];
                fma2(acc0[r], a, w0);
                fma2(acc1[r], a, w1);
            }
        }
    }
    float* outp = g_part + (size_t)blockIdx.y * BB * Nout;
#pragma unroll
    for (int r = 0; r < RP2; r++) {
        float2 v0 = upk(acc0[r]); float2 v1 = upk(acc1[r]);
        int row = ty * RP2 * 2 + 2 * r;
        outp[row * Nout + c0]             = v0.x;
        outp[(row + 1) * Nout + c0]       = v0.y;
        outp[row * Nout + c0 + TXN]       = v1.x;
        outp[(row + 1) * Nout + c0 + TXN] = v1.y;
    }
}

// ---------------- reduce 8 partials (+bias/+Xenc) + LSTM cell update -------
// grid 128, block 256 (32768 cells). gates layout: i,f,g,o at d, d+1024, ...
__global__ __launch_bounds__(256) void k_lstm_reduce(
    const float* __restrict__ bias, int use_xadd, int t, int store_enc)
{
    int idx = blockIdx.x * 256 + threadIdx.x;     // b*1024 + d
    int b = idx >> 10, d = idx & 1023;
    const float* xadd = g_Xenc + (size_t)t * BB * G4;
    float gv[4];
#pragma unroll
    for (int g = 0; g < 4; g++) {
        int off = b * G4 + g * DH + d;
        float s = bias ? bias[g * DH + d] : 0.f;
        if (use_xadd) s += xadd[off];
#pragma unroll
        for (int sp = 0; sp < 8; sp++) s += g_part[sp * (BB * G4) + off];
        gv[g] = s;
    }
    float cold = g_c[idx];
    float cn = sigm(gv[1]) * cold + sigm(gv[0]) * tanhf(gv[2]);
    float hn = sigm(gv[3]) * tanhf(cn);
    g_c[idx] = cn;
    g_h[idx] = hn;
    if (store_enc) g_enc_outs[(b * LL + t) * DH + d] = hn;
}

// ---------------- reduce comb partials + bias + relu -> g_inp --------------
__global__ __launch_bounds__(256) void k_comb_reduce(const float* __restrict__ bias)
{
    int idx = blockIdx.x * 256 + threadIdx.x;     // b*1024 + d
    int d = idx & 1023;
    float s = bias[d];
#pragma unroll
    for (int sp = 0; sp < 8; sp++) s += g_part[sp * (BB * DH) + idx];
    g_inp[idx] = fmaxf(s, 0.f);
}

// ---------------- attention: embed gather + scores + softmax + ctx ---------
// grid 32 (one block per batch row), block 256.
__global__ __launch_bounds__(256) void k_attn(
    const float* __restrict__ dec_embed, const float* __restrict__ attn_w,
    const float* __restrict__ attn_b)
{
    int b = blockIdx.x, tid = threadIdx.x;
    __shared__ float se[DH], sh[DH], sc[LL], sp_[4][LL], red[128];
    int tok = g_tok[b];
    for (int k = tid; k < DH; k += 256) {
        float e = dec_embed[(size_t)tok * DH + k];
        se[k] = e;
        g_e[b * DH + k] = e;
        sh[k] = g_h[b * DH + k];
    }
    __syncthreads();

    // scores over L=64 (threads: 64 cols x 4 K-groups of 512)
    int l = tid & 63, kg = tid >> 6;
    const float* src = (kg < 2) ? (se + kg * 512) : (sh + (kg - 2) * 512);
    const float* wbase = attn_w + (size_t)(kg * 512) * LL + l;
    float p = 0.f;
    for (int kk = 0; kk < 512; kk++)
        p += src[kk] * wbase[(size_t)kk * LL];
    sp_[kg][l] = p;
    __syncthreads();
    if (tid < 64)
        sc[tid] = sp_[0][tid] + sp_[1][tid] + sp_[2][tid] + sp_[3][tid] + attn_b[tid];
    __syncthreads();

    // softmax over 64
    if (tid < 64) red[tid] = sc[tid];
    __syncthreads();
    for (int off = 32; off >= 1; off >>= 1) {
        if (tid < off) red[tid] = fmaxf(red[tid], red[tid + off]);
        __syncthreads();
    }
    float mx = red[0];
    __syncthreads();
    if (tid < 64) { float e = expf(sc[tid] - mx); sc[tid] = e; red[tid] = e; }
    __syncthreads();
    for (int off = 32; off >= 1; off >>= 1) {
        if (tid < off) red[tid] += red[tid + off];
        __syncthreads();
    }
    float inv = 1.f / red[0];
    __syncthreads();
    if (tid < 64) sc[tid] *= inv;
    __syncthreads();

    // ctx[d] = sum_l aw[l] * enc_outs[b][l][d]
    float acc[4] = {0, 0, 0, 0};
#pragma unroll 4
    for (int l2 = 0; l2 < LL; l2++) {
        float a = sc[l2];
        const float* eo = g_enc_outs + (size_t)(b * LL + l2) * DH;
#pragma unroll
        for (int j = 0; j < 4; j++)
            acc[j] += a * eo[tid + j * 256];
    }
#pragma unroll
    for (int j = 0; j < 4; j++) g_ctx[b * DH + tid + j * 256] = acc[j];
}

// ---------------- output projection: logits -> d_out -----------------------
// grid 125, block 256.  Each thread: 4 cols x 8 rows (f32x2 pairs). K=1024.
__global__ __launch_bounds__(256) void k_outproj(
    const float* __restrict__ w, const float* __restrict__ bias,
    float* __restrict__ out, int t)
{
    __shared__ __align__(16) float As[32][34];
    int tid = threadIdx.x;
    int tx = tid & 63, ty = tid >> 6;
    int cb = blockIdx.x * 256 + tx;
    int lb = tid >> 3, lk = (tid & 7) * 4;

    ull acc[4][4];
#pragma unroll
    for (int j = 0; j < 4; j++)
#pragma unroll
        for (int r = 0; r < 4; r++) acc[j][r] = 0;

    for (int kc = 0; kc < DH; kc += 32) {
        __syncthreads();
        float4 v = *(const float4*)(g_h + lb * DH + kc + lk);
        As[lk + 0][lb] = v.x; As[lk + 1][lb] = v.y;
        As[lk + 2][lb] = v.z; As[lk + 3][lb] = v.w;
        __syncthreads();
#pragma unroll 4
        for (int kk = 0; kk < 32; kk++) {
            const float* wrow = w + (size_t)(kc + kk) * VV + cb;
            ull w0 = pk2(wrow[0]);
            ull w1 = pk2(wrow[64]);
            ull w2 = pk2(wrow[128]);
            ull w3 = pk2(wrow[192]);
            const ull* ar = (const ull*)&As[kk][ty * 8];
#pragma unroll
            for (int r = 0; r < 4; r++) {
                ull a = ar[r];
                fma2(acc[0][r], a, w0);
                fma2(acc[1][r], a, w1);
                fma2(acc[2][r], a, w2);
                fma2(acc[3][r], a, w3);
            }
        }
    }
#pragma unroll
    for (int j = 0; j < 4; j++) {
        int c = cb + j * 64;
        float bv = bias[c];
#pragma unroll
        for (int r = 0; r < 4; r++) {
            float2 v = upk(acc[j][r]);
            int row = ty * 8 + 2 * r;
            out[((size_t)(row * LL + t)) * VV + c]       = v.x + bv;
            out[((size_t)((row + 1) * LL + t)) * VV + c] = v.y + bv;
        }
    }
}

// ---------------- finalize: log_softmax in place + argmax -> g_tok ---------
// grid 32 (one per batch row), block 256.
__global__ __launch_bounds__(256) void k_final(float* __restrict__ out, int t)
{
    int b = blockIdx.x, tid = threadIdx.x;
    float* row = out + ((size_t)(b * LL + t)) * VV;
    __shared__ float sm[256];
    __shared__ int si[256];

    float m = -1e30f; int mi = 0;
    for (int i = tid; i < VV; i += 256) {
        float v = row[i];
        if (v > m) { m = v; mi = i; }     // strict > keeps first occurrence
    }
    sm[tid] = m; si[tid] = mi;
    __syncthreads();
    for (int off = 128; off >= 1; off >>= 1) {
        if (tid < off) {
            float o = sm[tid + off]; int oi = si[tid + off];
            if (o > sm[tid] || (o == sm[tid] && oi < si[tid])) { sm[tid] = o; si[tid] = oi; }
        }
        __syncthreads();
    }
    float mx = sm[0]; int am = si[0];
    __syncthreads();

    float s = 0.f;
    for (int i = tid; i < VV; i += 256) s += expf(row[i] - mx);
    sm[tid] = s;
    __syncthreads();
    for (int off = 128; off >= 1; off >>= 1) {
        if (tid < off) sm[tid] += sm[tid + off];
        __syncthreads();
    }
    float lse = mx + logf(sm[0]);

    for (int i = tid; i < VV; i += 256) row[i] -= lse;
    if (tid == 0) g_tok[b] = am;
}

// ---------------- host launcher --------------------------------------------
extern "C" void kernel_launch(void* const* d_in, const int* in_sizes, int n_in,
                              void* d_out, int out_size)
{
    (void)in_sizes; (void)n_in; (void)out_size;
    const int*   x         = (const int*)  d_in[0];
    const float* enc_embed = (const float*)d_in[1];
    const float* enc_wx    = (const float*)d_in[2];
    const float* enc_wh    = (const float*)d_in[3];
    const float* enc_b     = (const float*)d_in[4];
    const float* dec_embed = (const float*)d_in[5];
    const float* attn_w    = (const float*)d_in[6];
    const float* attn_b    = (const float*)d_in[7];
    const float* comb_w    = (const float*)d_in[8];
    const float* comb_b    = (const float*)d_in[9];
    const float* dec_wx    = (const float*)d_in[10];
    const float* dec_wh    = (const float*)d_in[11];
    const float* dec_b     = (const float*)d_in[12];
    const float* out_w     = (const float*)d_in[13];
    const float* out_b     = (const float*)d_in[14];
    float* out = (float*)d_out;
    const int BIG = 1 << 30;

    // encoder
    k_init<<<128, 256>>>(0);
    k_enc_pre<<<dim3(32, 1, 64), 256>>>(x, enc_embed, enc_wx, enc_b);
    for (int t = 0; t < LL; t++) {
        // partial: h @ enc_wh  (K=1024, splits of 128)
        k_gemm32<128><<<dim3(32, 8), 256>>>(0, enc_wh, enc_wh, BIG, G4, 128, G4);
        k_lstm_reduce<<<128, 256>>>(nullptr, 1, t, 1);
    }

    // decoder
    k_init<<<128, 256>>>(1);
    for (int t = 0; t < LL; t++) {
        k_attn<<<32, 256>>>(dec_embed, attn_w, attn_b);
        // comb: cat(e,ctx) @ comb_w  (K=2048, splits of 256, N=1024)
        k_gemm32<64><<<dim3(16, 8), 256>>>(1, comb_w, comb_w, BIG, DH, 256, DH);
        k_comb_reduce<<<128, 256>>>(comb_b);
        // gates: inp @ dec_wx + h @ dec_wh  (K=2048 stacked, splits of 256)
        k_gemm32<128><<<dim3(32, 8), 256>>>(2, dec_wx, dec_wh, DH, G4, 256, G4);
        k_lstm_reduce<<<128, 256>>>(dec_b, 0, t, 0);
        // logits + log_softmax + argmax feedback
        k_outproj<<<125, 256>>>(out_w, out_b, out, t);
        k_final<<<32, 256>>>(out, t);
    }
}

// round 5
// speedup vs baseline: 1.2558x; 1.2558x over previous
#include <cuda_runtime.h>
#include <math.h>

// Problem constants
#define BB 32
#define LL 64
#define EE 512
#define DH 1024
#define G4 4096
#define VV 32000

typedef unsigned long long ull;

// ---------------- scratch (device globals; no allocation allowed) ----------
__device__ __align__(16) float g_Xenc[LL * BB * G4];      // embed@enc_wx + enc_b
__device__ __align__(16) float g_enc_outs[BB * LL * DH];  // encoder hidden states
__device__ __align__(16) float g_part[8 * BB * G4];       // split-K partials
__device__ __align__(16) float g_h[BB * DH];
__device__ __align__(16) float g_c[BB * DH];
__device__ __align__(16) float g_e[BB * DH];
__device__ __align__(16) float g_ctx[BB * DH];
__device__ __align__(16) float g_inp[BB * DH];
__device__ int   g_tok[BB];
__device__ float g_fm[BB][8];   // per-chunk max
__device__ float g_fs[BB][8];   // per-chunk sum exp(x - chunkmax)
__device__ int   g_fi[BB][8];   // per-chunk argmax

// ---------------- f32x2 helpers (sm_103a packed FMA) -----------------------
__device__ __forceinline__ ull pk2(float w) {
    ull r; asm("mov.b64 %0, {%1, %1};" : "=l"(r) : "f"(w)); return r;
}
__device__ __forceinline__ void fma2(ull& d, ull a, ull b) {
    asm("fma.rn.f32x2 %0, %1, %2, %0;" : "+l"(d) : "l"(a), "l"(b));
}
__device__ __forceinline__ float2 upk(ull v) {
    float2 f; asm("mov.b64 {%0, %1}, %2;" : "=f"(f.x), "=f"(f.y) : "l"(v)); return f;
}
__device__ __forceinline__ float sigm(float x) { return 1.0f / (1.0f + expf(-x)); }

// ---------------- init: zero h/c (+ optional tok=127) ----------------------
__global__ void k_init(int settok) {
    int idx = blockIdx.x * blockDim.x + threadIdx.x;
    if (idx < BB * DH) { g_h[idx] = 0.f; g_c[idx] = 0.f; }
    if (settok && idx < BB) g_tok[idx] = 127;
}

// ---------------- one-time: Xenc[t] = embed(x[:,t]) @ enc_wx + enc_b -------
// grid (32, 1, 64), block 256. 128 cols/block, thread = 4 consecutive cols x 4 rows.
__global__ __launch_bounds__(256) void k_enc_pre(
    const int* __restrict__ x, const float* __restrict__ emb,
    const float* __restrict__ wx, const float* __restrict__ bias)
{
    __shared__ __align__(16) float As[32][34];
    int tid = threadIdx.x;
    int t = blockIdx.z;
    int txq = tid & 31, ty = tid >> 5;          // 32 col-quads x 8 row-groups(4)
    int c0 = blockIdx.x * 128 + txq * 4;
    int lb = tid >> 3, lk = (tid & 7) * 4;
    int tok = x[lb * LL + t];
    const float* arow = emb + (size_t)tok * EE;

    ull acc[4][2];
#pragma unroll
    for (int j = 0; j < 4; j++) { acc[j][0] = 0; acc[j][1] = 0; }

    for (int kc = 0; kc < EE; kc += 32) {
        __syncthreads();
        float4 v = *(const float4*)(arow + kc + lk);
        As[lk + 0][lb] = v.x; As[lk + 1][lb] = v.y;
        As[lk + 2][lb] = v.z; As[lk + 3][lb] = v.w;
        __syncthreads();
#pragma unroll 8
        for (int kk = 0; kk < 32; kk++) {
            float4 w4 = *(const float4*)(wx + (size_t)(kc + kk) * G4 + c0);
            ull wp0 = pk2(w4.x), wp1 = pk2(w4.y), wp2 = pk2(w4.z), wp3 = pk2(w4.w);
            ull a0 = *(const ull*)&As[kk][ty * 4];
            ull a1 = *(const ull*)&As[kk][ty * 4 + 2];
            fma2(acc[0][0], a0, wp0); fma2(acc[0][1], a1, wp0);
            fma2(acc[1][0], a0, wp1); fma2(acc[1][1], a1, wp1);
            fma2(acc[2][0], a0, wp2); fma2(acc[2][1], a1, wp2);
            fma2(acc[3][0], a0, wp3); fma2(acc[3][1], a1, wp3);
        }
    }
    float4 bv = *(const float4*)(bias + c0);
    float bj[4] = {bv.x, bv.y, bv.z, bv.w};
    float* outt = g_Xenc + (size_t)t * BB * G4;
#pragma unroll
    for (int j = 0; j < 4; j++) {
        int c = c0 + j;
#pragma unroll
        for (int rp = 0; rp < 2; rp++) {
            float2 v = upk(acc[j][rp]);
            int row = ty * 4 + rp * 2;
            outt[row * G4 + c]       = v.x + bj[j];
            outt[(row + 1) * G4 + c] = v.y + bj[j];
        }
    }
}

// ---------------- generic split-K partial GEMM, M=32, float4 weights -------
// amode: 0 = A=g_h ; 1 = A=cat(g_e, g_ctx) ; 2 = A=cat(g_inp, g_h)
// grid (Nout/NTILE, splits). Partial s -> g_part[s][b][0..Nout).
template <int NTILE>
__global__ __launch_bounds__(256) void k_gemm_f4(
    int amode, const float* __restrict__ W1, const float* __restrict__ W2,
    int Wsplit, int ldW, int KC, int Nout)
{
    constexpr int TQ  = NTILE / 4;   // threads in col dim (4 cols each)
    constexpr int RG  = 256 / TQ;    // row groups
    constexpr int RPG = 32 / RG;     // rows per group (even)
    constexpr int NRP = RPG / 2;     // f32x2 row-pairs per thread
    __shared__ __align__(16) float As[32][34];
    int tid = threadIdx.x;
    int txq = tid % TQ, ty = tid / TQ;
    int c0 = blockIdx.x * NTILE + txq * 4;
    int k0 = blockIdx.y * KC;

    const float* A1; const float* A2; int Asplit;
    if (amode == 0)      { A1 = g_h;   A2 = g_h;   Asplit = 1 << 30; }
    else if (amode == 1) { A1 = g_e;   A2 = g_ctx; Asplit = DH; }
    else                 { A1 = g_inp; A2 = g_h;   Asplit = DH; }
    const float* Ab = (k0 < Asplit) ? (A1 + k0) : (A2 + (k0 - Asplit));
    const float* Wb = (k0 < Wsplit) ? (W1 + (size_t)k0 * ldW)
                                    : (W2 + (size_t)(k0 - Wsplit) * ldW);
    int lb = tid >> 3, lk = (tid & 7) * 4;

    ull acc[4][NRP];
#pragma unroll
    for (int j = 0; j < 4; j++)
#pragma unroll
        for (int rp = 0; rp < NRP; rp++) acc[j][rp] = 0;

    for (int kc = 0; kc < KC; kc += 32) {
        __syncthreads();
        float4 v = *(const float4*)(Ab + lb * DH + kc + lk);
        As[lk + 0][lb] = v.x; As[lk + 1][lb] = v.y;
        As[lk + 2][lb] = v.z; As[lk + 3][lb] = v.w;
        __syncthreads();
#pragma unroll 8
        for (int kk = 0; kk < 32; kk++) {
            float4 w4 = *(const float4*)(Wb + (size_t)(kc + kk) * ldW + c0);
            ull wp0 = pk2(w4.x), wp1 = pk2(w4.y), wp2 = pk2(w4.z), wp3 = pk2(w4.w);
#pragma unroll
            for (int rp = 0; rp < NRP; rp++) {
                ull a = *(const ull*)&As[kk][ty * RPG + rp * 2];
                fma2(acc[0][rp], a, wp0);
                fma2(acc[1][rp], a, wp1);
                fma2(acc[2][rp], a, wp2);
                fma2(acc[3][rp], a, wp3);
            }
        }
    }
    float* outp = g_part + (size_t)blockIdx.y * BB * Nout;
#pragma unroll
    for (int j = 0; j < 4; j++) {
        int c = c0 + j;
#pragma unroll
        for (int rp = 0; rp < NRP; rp++) {
            float2 v = upk(acc[j][rp]);
            int row = ty * RPG + rp * 2;
            outp[row * Nout + c]       = v.x;
            outp[(row + 1) * Nout + c] = v.y;
        }
    }
}

// ---------------- reduce 8 partials (+bias/+Xenc) + LSTM cell (float4) -----
// grid 32, block 256: 8192 threads x 4 cells.
__global__ __launch_bounds__(256) void k_lstm_reduce(
    const float* __restrict__ bias, int use_xadd, int t, int store_enc)
{
    int i4 = blockIdx.x * 256 + threadIdx.x;    // 0..8191
    int base = i4 * 4;
    int b = base >> 10, d = base & 1023;
    const float4* xadd = (const float4*)(g_Xenc + (size_t)t * BB * G4);
    float4 gv[4];
#pragma unroll
    for (int g = 0; g < 4; g++) {
        int off4 = (b * G4 + g * DH + d) >> 2;
        float4 s = bias ? ((const float4*)bias)[(g * DH + d) >> 2]
                        : make_float4(0.f, 0.f, 0.f, 0.f);
        if (use_xadd) {
            float4 xv = xadd[off4];
            s.x += xv.x; s.y += xv.y; s.z += xv.z; s.w += xv.w;
        }
#pragma unroll
        for (int sp = 0; sp < 8; sp++) {
            float4 p = ((const float4*)g_part)[sp * (BB * G4 / 4) + off4];
            s.x += p.x; s.y += p.y; s.z += p.z; s.w += p.w;
        }
        gv[g] = s;
    }
    float4 cold = ((const float4*)g_c)[i4];
    float4 cn, hn;
    {
        float* iv = (float*)&gv[0]; float* fv = (float*)&gv[1];
        float* gg = (float*)&gv[2]; float* ov = (float*)&gv[3];
        float* cp = (float*)&cold; float* cnp = (float*)&cn; float* hnp = (float*)&hn;
#pragma unroll
        for (int j = 0; j < 4; j++) {
            float cc = sigm(fv[j]) * cp[j] + sigm(iv[j]) * tanhf(gg[j]);
            cnp[j] = cc;
            hnp[j] = sigm(ov[j]) * tanhf(cc);
        }
    }
    ((float4*)g_c)[i4] = cn;
    ((float4*)g_h)[i4] = hn;
    if (store_enc)
        ((float4*)g_enc_outs)[((b * LL + t) * DH + d) >> 2] = hn;
}

// ---------------- reduce comb partials + bias + relu -> g_inp (float4) -----
__global__ __launch_bounds__(256) void k_comb_reduce(const float* __restrict__ bias)
{
    int i4 = blockIdx.x * 256 + threadIdx.x;    // 0..8191 (BB*DH/4)
    int d = (i4 * 4) & 1023;
    float4 s = ((const float4*)bias)[d >> 2];
#pragma unroll
    for (int sp = 0; sp < 8; sp++) {
        float4 p = ((const float4*)g_part)[sp * (BB * DH / 4) + i4];
        s.x += p.x; s.y += p.y; s.z += p.z; s.w += p.w;
    }
    s.x = fmaxf(s.x, 0.f); s.y = fmaxf(s.y, 0.f);
    s.z = fmaxf(s.z, 0.f); s.w = fmaxf(s.w, 0.f);
    ((float4*)g_inp)[i4] = s;
}

// ---------------- attention: embed gather + scores + softmax + ctx ---------
// grid 32 (one block per batch row), block 256.
__global__ __launch_bounds__(256) void k_attn(
    const float* __restrict__ dec_embed, const float* __restrict__ attn_w,
    const float* __restrict__ attn_b)
{
    int b = blockIdx.x, tid = threadIdx.x;
    __shared__ float se[DH], sh[DH], sc[LL], sp_[4][LL], red[128];
    int tok = g_tok[b];
    for (int k = tid; k < DH; k += 256) {
        float e = dec_embed[(size_t)tok * DH + k];
        se[k] = e;
        g_e[b * DH + k] = e;
        sh[k] = g_h[b * DH + k];
    }
    __syncthreads();

    // scores over L=64 (threads: 64 cols x 4 K-groups of 512), 4-way ILP
    int l = tid & 63, kg = tid >> 6;
    const float* src = (kg < 2) ? (se + kg * 512) : (sh + (kg - 2) * 512);
    const float* wbase = attn_w + (size_t)(kg * 512) * LL + l;
    float p0 = 0.f, p1 = 0.f, p2 = 0.f, p3 = 0.f;
#pragma unroll 4
    for (int kk = 0; kk < 512; kk += 4) {
        p0 += src[kk + 0] * wbase[(size_t)(kk + 0) * LL];
        p1 += src[kk + 1] * wbase[(size_t)(kk + 1) * LL];
        p2 += src[kk + 2] * wbase[(size_t)(kk + 2) * LL];
        p3 += src[kk + 3] * wbase[(size_t)(kk + 3) * LL];
    }
    sp_[kg][l] = (p0 + p1) + (p2 + p3);
    __syncthreads();
    if (tid < 64)
        sc[tid] = sp_[0][tid] + sp_[1][tid] + sp_[2][tid] + sp_[3][tid] + attn_b[tid];
    __syncthreads();

    // softmax over 64
    if (tid < 64) red[tid] = sc[tid];
    __syncthreads();
    for (int off = 32; off >= 1; off >>= 1) {
        if (tid < off) red[tid] = fmaxf(red[tid], red[tid + off]);
        __syncthreads();
    }
    float mx = red[0];
    __syncthreads();
    if (tid < 64) { float e = expf(sc[tid] - mx); sc[tid] = e; red[tid] = e; }
    __syncthreads();
    for (int off = 32; off >= 1; off >>= 1) {
        if (tid < off) red[tid] += red[tid + off];
        __syncthreads();
    }
    float inv = 1.f / red[0];
    __syncthreads();
    if (tid < 64) sc[tid] *= inv;
    __syncthreads();

    // ctx[d] = sum_l aw[l] * enc_outs[b][l][d]
    float acc[4] = {0, 0, 0, 0};
#pragma unroll 4
    for (int l2 = 0; l2 < LL; l2++) {
        float a = sc[l2];
        const float* eo = g_enc_outs + (size_t)(b * LL + l2) * DH;
#pragma unroll
        for (int j = 0; j < 4; j++)
            acc[j] += a * eo[tid + j * 256];
    }
#pragma unroll
    for (int j = 0; j < 4; j++) g_ctx[b * DH + tid + j * 256] = acc[j];
}

// ---------------- output projection: logits -> d_out -----------------------
// grid 250, block 256. thread = 4 consecutive cols x 4 rows. K=1024.
__global__ __launch_bounds__(256) void k_outproj(
    const float* __restrict__ w, const float* __restrict__ bias,
    float* __restrict__ out, int t)
{
    __shared__ __align__(16) float As[32][34];
    int tid = threadIdx.x;
    int txq = tid & 31, ty = tid >> 5;
    int c0 = blockIdx.x * 128 + txq * 4;
    int lb = tid >> 3, lk = (tid & 7) * 4;

    ull acc[4][2];
#pragma unroll
    for (int j = 0; j < 4; j++) { acc[j][0] = 0; acc[j][1] = 0; }

    for (int kc = 0; kc < DH; kc += 32) {
        __syncthreads();
        float4 v = *(const float4*)(g_h + lb * DH + kc + lk);
        As[lk + 0][lb] = v.x; As[lk + 1][lb] = v.y;
        As[lk + 2][lb] = v.z; As[lk + 3][lb] = v.w;
        __syncthreads();
#pragma unroll 4
        for (int kk = 0; kk < 32; kk++) {
            float4 w4 = __ldcs((const float4*)(w + (size_t)(kc + kk) * VV + c0));
            ull wp0 = pk2(w4.x), wp1 = pk2(w4.y), wp2 = pk2(w4.z), wp3 = pk2(w4.w);
            ull a0 = *(const ull*)&As[kk][ty * 4];
            ull a1 = *(const ull*)&As[kk][ty * 4 + 2];
            fma2(acc[0][0], a0, wp0); fma2(acc[0][1], a1, wp0);
            fma2(acc[1][0], a0, wp1); fma2(acc[1][1], a1, wp1);
            fma2(acc[2][0], a0, wp2); fma2(acc[2][1], a1, wp2);
            fma2(acc[3][0], a0, wp3); fma2(acc[3][1], a1, wp3);
        }
    }
    float4 bv = *(const float4*)(bias + c0);
    float bj[4] = {bv.x, bv.y, bv.z, bv.w};
#pragma unroll
    for (int j = 0; j < 4; j++) {
        int c = c0 + j;
#pragma unroll
        for (int rp = 0; rp < 2; rp++) {
            float2 v = upk(acc[j][rp]);
            int row = ty * 4 + rp * 2;
            out[((size_t)(row * LL + t)) * VV + c]       = v.x + bj[j];
            out[((size_t)((row + 1) * LL + t)) * VV + c] = v.y + bj[j];
        }
    }
}

// ---------------- finalize A: per-chunk max/argmax + expsum -----------------
// grid (8, 32): chunk j (4000 cols) of batch row b.
__global__ __launch_bounds__(256) void k_final_part(const float* __restrict__ out, int t)
{
    int j = blockIdx.x, b = blockIdx.y, tid = threadIdx.x;
    const float* row = out + ((size_t)(b * LL + t)) * VV;
    int lo = j * 4000, hi = lo + 4000;
    __shared__ float sm[256];
    __shared__ int si[256];

    float m = -1e30f; int mi = lo;
    for (int i = lo + tid; i < hi; i += 256) {
        float v = row[i];
        if (v > m) { m = v; mi = i; }
    }
    sm[tid] = m; si[tid] = mi;
    __syncthreads();
    for (int off = 128; off >= 1; off >>= 1) {
        if (tid < off) {
            float o = sm[tid + off]; int oi = si[tid + off];
            if (o > sm[tid] || (o == sm[tid] && oi < si[tid])) { sm[tid] = o; si[tid] = oi; }
        }
        __syncthreads();
    }
    float mx = sm[0]; int am = si[0];
    __syncthreads();

    float s = 0.f;
    for (int i = lo + tid; i < hi; i += 256) s += expf(row[i] - mx);
    sm[tid] = s;
    __syncthreads();
    for (int off = 128; off >= 1; off >>= 1) {
        if (tid < off) sm[tid] += sm[tid + off];
        __syncthreads();
    }
    if (tid == 0) {
        g_fm[b][j] = mx;
        g_fs[b][j] = sm[0];
        g_fi[b][j] = am;
    }
}

// ---------------- finalize B: merge partials, subtract lse, emit token -----
// grid (8, 32).
__global__ __launch_bounds__(256) void k_final_sub(float* __restrict__ out, int t)
{
    int j = blockIdx.x, b = blockIdx.y, tid = threadIdx.x;
    float M = -1e30f;
#pragma unroll
    for (int jj = 0; jj < 8; jj++) M = fmaxf(M, g_fm[b][jj]);
    float S = 0.f;
#pragma unroll
    for (int jj = 0; jj < 8; jj++) S += g_fs[b][jj] * expf(g_fm[b][jj] - M);
    float lse = M + logf(S);

    float* row = out + ((size_t)(b * LL + t)) * VV;
    int lo = j * 4000, hi = lo + 4000;
    for (int i = lo + tid; i < hi; i += 256) row[i] -= lse;

    if (j == 0 && tid == 0) {
        float bm = -1e30f; int bi = 0;
#pragma unroll
        for (int jj = 0; jj < 8; jj++) {
            if (g_fm[b][jj] > bm) { bm = g_fm[b][jj]; bi = g_fi[b][jj]; }
        }
        g_tok[b] = bi;   // first-max-wins ties preserved by chunk order + strict >
    }
}

// ---------------- host launcher --------------------------------------------
extern "C" void kernel_launch(void* const* d_in, const int* in_sizes, int n_in,
                              void* d_out, int out_size)
{
    (void)in_sizes; (void)n_in; (void)out_size;
    const int*   x         = (const int*)  d_in[0];
    const float* enc_embed = (const float*)d_in[1];
    const float* enc_wx    = (const float*)d_in[2];
    const float* enc_wh    = (const float*)d_in[3];
    const float* enc_b     = (const float*)d_in[4];
    const float* dec_embed = (const float*)d_in[5];
    const float* attn_w    = (const float*)d_in[6];
    const float* attn_b    = (const float*)d_in[7];
    const float* comb_w    = (const float*)d_in[8];
    const float* comb_b    = (const float*)d_in[9];
    const float* dec_wx    = (const float*)d_in[10];
    const float* dec_wh    = (const float*)d_in[11];
    const float* dec_b     = (const float*)d_in[12];
    const float* out_w     = (const float*)d_in[13];
    const float* out_b     = (const float*)d_in[14];
    float* out = (float*)d_out;
    const int BIG = 1 << 30;

    // encoder
    k_init<<<128, 256>>>(0);
    k_enc_pre<<<dim3(32, 1, 64), 256>>>(x, enc_embed, enc_wx, enc_b);
    for (int t = 0; t < LL; t++) {
        k_gemm_f4<128><<<dim3(32, 8), 256>>>(0, enc_wh, enc_wh, BIG, G4, 128, G4);
        k_lstm_reduce<<<32, 256>>>(nullptr, 1, t, 1);
    }

    // decoder
    k_init<<<128, 256>>>(1);
    for (int t = 0; t < LL; t++) {
        k_attn<<<32, 256>>>(dec_embed, attn_w, attn_b);
        k_gemm_f4<64><<<dim3(16, 8), 256>>>(1, comb_w, comb_w, BIG, DH, 256, DH);
        k_comb_reduce<<<32, 256>>>(comb_b);
        k_gemm_f4<128><<<dim3(32, 8), 256>>>(2, dec_wx, dec_wh, DH, G4, 256, G4);
        k_lstm_reduce<<<32, 256>>>(dec_b, 0, t, 0);
        k_outproj<<<250, 256>>>(out_w, out_b, out, t);
        k_final_part<<<dim3(8, 32), 256>>>(out, t);
        k_final_sub<<<dim3(8, 32), 256>>>(out, t);
    }
}

// round 6
// speedup vs baseline: 2.0514x; 1.6335x over previous
#include <cuda_runtime.h>
#include <math.h>

// Problem constants
#define BB 32
#define LL 64
#define EE 512
#define DH 1024
#define G4 4096
#define VV 32000

typedef unsigned long long ull;

// ---------------- scratch (device globals; no allocation allowed) ----------
__device__ __align__(16) float g_Xenc[LL * BB * G4];      // embed@enc_wx + enc_b
__device__ __align__(16) float g_enc_outs[BB * LL * DH];  // encoder hidden states
__device__ __align__(16) float g_part[8 * BB * G4];       // split-K partials
__device__ __align__(16) float g_h[BB * DH];
__device__ __align__(16) float g_c[BB * DH];
__device__ __align__(16) float g_e[BB * DH];
__device__ __align__(16) float g_ctx[BB * DH];
__device__ __align__(16) float g_inp[BB * DH];
__device__ int   g_tok[BB];
__device__ float g_fm[BB][8];   // per-chunk max
__device__ float g_fs[BB][8];   // per-chunk sum exp(x - chunkmax)
__device__ int   g_fi[BB][8];   // per-chunk argmax

// ---------------- f32x2 helpers (sm_103a packed FMA) -----------------------
__device__ __forceinline__ ull pk2(float w) {
    ull r; asm("mov.b64 %0, {%1, %1};" : "=l"(r) : "f"(w)); return r;
}
__device__ __forceinline__ void fma2(ull& d, ull a, ull b) {
    asm("fma.rn.f32x2 %0, %1, %2, %0;" : "+l"(d) : "l"(a), "l"(b));
}
__device__ __forceinline__ float2 upk(ull v) {
    float2 f; asm("mov.b64 {%0, %1}, %2;" : "=f"(f.x), "=f"(f.y) : "l"(v)); return f;
}
__device__ __forceinline__ float sigm(float x) { return 1.0f / (1.0f + expf(-x)); }

// ---------------- init: zero h/c (+ optional tok=127) ----------------------
__global__ void k_init(int settok) {
    int idx = blockIdx.x * blockDim.x + threadIdx.x;
    if (idx < BB * DH) { g_h[idx] = 0.f; g_c[idx] = 0.f; }
    if (settok && idx < BB) g_tok[idx] = 127;
}

// ---------------- one-time: Xenc[t] = embed(x[:,t]) @ enc_wx + enc_b -------
// grid (32, 1, 64), block 256. (one-time cost; massive grid parallelism)
__global__ __launch_bounds__(256) void k_enc_pre(
    const int* __restrict__ x, const float* __restrict__ emb,
    const float* __restrict__ wx, const float* __restrict__ bias)
{
    __shared__ __align__(16) float As[32][34];
    int tid = threadIdx.x;
    int t = blockIdx.z;
    int txq = tid & 31, ty = tid >> 5;
    int c0 = blockIdx.x * 128 + txq * 4;
    int lb = tid >> 3, lk = (tid & 7) * 4;
    int tok = x[lb * LL + t];
    const float* arow = emb + (size_t)tok * EE;

    ull acc[4][2];
#pragma unroll
    for (int j = 0; j < 4; j++) { acc[j][0] = 0; acc[j][1] = 0; }

    for (int kc = 0; kc < EE; kc += 32) {
        __syncthreads();
        float4 v = *(const float4*)(arow + kc + lk);
        As[lk + 0][lb] = v.x; As[lk + 1][lb] = v.y;
        As[lk + 2][lb] = v.z; As[lk + 3][lb] = v.w;
        __syncthreads();
#pragma unroll 8
        for (int kk = 0; kk < 32; kk++) {
            float4 w4 = *(const float4*)(wx + (size_t)(kc + kk) * G4 + c0);
            ull wp0 = pk2(w4.x), wp1 = pk2(w4.y), wp2 = pk2(w4.z), wp3 = pk2(w4.w);
            ull a0 = *(const ull*)&As[kk][ty * 4];
            ull a1 = *(const ull*)&As[kk][ty * 4 + 2];
            fma2(acc[0][0], a0, wp0); fma2(acc[0][1], a1, wp0);
            fma2(acc[1][0], a0, wp1); fma2(acc[1][1], a1, wp1);
            fma2(acc[2][0], a0, wp2); fma2(acc[2][1], a1, wp2);
            fma2(acc[3][0], a0, wp3); fma2(acc[3][1], a1, wp3);
        }
    }
    float4 bv = *(const float4*)(bias + c0);
    float bj[4] = {bv.x, bv.y, bv.z, bv.w};
    float* outt = g_Xenc + (size_t)t * BB * G4;
#pragma unroll
    for (int j = 0; j < 4; j++) {
        int c = c0 + j;
#pragma unroll
        for (int rp = 0; rp < 2; rp++) {
            float2 v = upk(acc[j][rp]);
            int row = ty * 4 + rp * 2;
            outt[row * G4 + c]       = v.x + bj[j];
            outt[(row + 1) * G4 + c] = v.y + bj[j];
        }
    }
}

// ---------------- smem-staged double-buffered GEMM, M=32, NTILE=64 ---------
// amode: 0 = A=g_h ; 1 = A=cat(g_e, g_ctx) ; 2 = A=cat(g_inp, g_h)
// grid (Nout/64, splits). Partial s -> g_part[s][b][0..Nout).
// Per-kk inner loop: LDS.128 (w pair-pack) + LDS.128 (a pair-pack) + 4 FMA2.
__global__ __launch_bounds__(256) void k_gemm_s(
    int amode, const float* __restrict__ W1, const float* __restrict__ W2,
    int Wsplit, int ldW, int KC, int Nout)
{
    __shared__ __align__(16) float Ws[2][32][64];
    __shared__ __align__(16) ull   Au[2][32][34];
    int tid = threadIdx.x;
    int cg = tid & 15, tr = tid >> 4;
    int cb = blockIdx.x * 64;
    int k0 = blockIdx.y * KC;

    const float* A1; const float* A2; int Asplit;
    if (amode == 0)      { A1 = g_h;   A2 = g_h;   Asplit = 1 << 30; }
    else if (amode == 1) { A1 = g_e;   A2 = g_ctx; Asplit = DH; }
    else                 { A1 = g_inp; A2 = g_h;   Asplit = DH; }
    const float* Ab = (k0 < Asplit) ? (A1 + k0) : (A2 + (k0 - Asplit));
    const float* Wb = (k0 < Wsplit) ? (W1 + (size_t)k0 * ldW)
                                    : (W2 + (size_t)(k0 - Wsplit) * ldW);

    int wr0 = tid >> 4, wc0 = (tid & 15) * 4;   // W loader: rows wr0 & wr0+16
    int lb = tid >> 3, lk = (tid & 7) * 4;       // A loader

    float4 w0 = *(const float4*)(Wb + (size_t)wr0 * ldW + cb + wc0);
    float4 w1 = *(const float4*)(Wb + (size_t)(wr0 + 16) * ldW + cb + wc0);
    float4 av = *(const float4*)(Ab + lb * DH + lk);

    ull acc[2][2] = {{0, 0}, {0, 0}};
    int buf = 0;
    for (int kc = 0; kc < KC; kc += 32) {
        *(float4*)&Ws[buf][wr0][wc0]      = w0;
        *(float4*)&Ws[buf][wr0 + 16][wc0] = w1;
        Au[buf][lk + 0][lb] = pk2(av.x);
        Au[buf][lk + 1][lb] = pk2(av.y);
        Au[buf][lk + 2][lb] = pk2(av.z);
        Au[buf][lk + 3][lb] = pk2(av.w);
        __syncthreads();
        if (kc + 32 < KC) {
            const float* wp = Wb + (size_t)(kc + 32) * ldW;
            w0 = *(const float4*)(wp + (size_t)wr0 * ldW + cb + wc0);
            w1 = *(const float4*)(wp + (size_t)(wr0 + 16) * ldW + cb + wc0);
            av = *(const float4*)(Ab + lb * DH + kc + 32 + lk);
        }
#pragma unroll
        for (int kk = 0; kk < 32; kk++) {
            ulonglong2 wv = *(const ulonglong2*)&Ws[buf][kk][cg * 4];
            ulonglong2 a2 = *(const ulonglong2*)&Au[buf][kk][tr * 2];
            fma2(acc[0][0], wv.x, a2.x); fma2(acc[0][1], wv.y, a2.x);
            fma2(acc[1][0], wv.x, a2.y); fma2(acc[1][1], wv.y, a2.y);
        }
        buf ^= 1;
    }
    float* outp = g_part + (size_t)blockIdx.y * BB * Nout;
    int r0 = tr * 2;
#pragma unroll
    for (int cp = 0; cp < 2; cp++) {
        int c = cb + cg * 4 + 2 * cp;
        float2 v0 = upk(acc[0][cp]);
        float2 v1 = upk(acc[1][cp]);
        *(float2*)&outp[(size_t)r0 * Nout + c]       = v0;
        *(float2*)&outp[(size_t)(r0 + 1) * Nout + c] = v1;
    }
}

// ---------------- output projection: logits -> d_out (same core) -----------
// grid 500, block 256. K=1024, no split, bias fused, __ldcs weight stream.
__global__ __launch_bounds__(256) void k_outproj(
    const float* __restrict__ w, const float* __restrict__ bias,
    float* __restrict__ out, int t)
{
    __shared__ __align__(16) float Ws[2][32][64];
    __shared__ __align__(16) ull   Au[2][32][34];
    int tid = threadIdx.x;
    int cg = tid & 15, tr = tid >> 4;
    int cb = blockIdx.x * 64;
    int wr0 = tid >> 4, wc0 = (tid & 15) * 4;
    int lb = tid >> 3, lk = (tid & 7) * 4;

    float4 w0 = __ldcs((const float4*)(w + (size_t)wr0 * VV + cb + wc0));
    float4 w1 = __ldcs((const float4*)(w + (size_t)(wr0 + 16) * VV + cb + wc0));
    float4 av = *(const float4*)(g_h + lb * DH + lk);

    ull acc[2][2] = {{0, 0}, {0, 0}};
    int buf = 0;
    for (int kc = 0; kc < DH; kc += 32) {
        *(float4*)&Ws[buf][wr0][wc0]      = w0;
        *(float4*)&Ws[buf][wr0 + 16][wc0] = w1;
        Au[buf][lk + 0][lb] = pk2(av.x);
        Au[buf][lk + 1][lb] = pk2(av.y);
        Au[buf][lk + 2][lb] = pk2(av.z);
        Au[buf][lk + 3][lb] = pk2(av.w);
        __syncthreads();
        if (kc + 32 < DH) {
            const float* wp = w + (size_t)(kc + 32) * VV;
            w0 = __ldcs((const float4*)(wp + (size_t)wr0 * VV + cb + wc0));
            w1 = __ldcs((const float4*)(wp + (size_t)(wr0 + 16) * VV + cb + wc0));
            av = *(const float4*)(g_h + lb * DH + kc + 32 + lk);
        }
#pragma unroll
        for (int kk = 0; kk < 32; kk++) {
            ulonglong2 wv = *(const ulonglong2*)&Ws[buf][kk][cg * 4];
            ulonglong2 a2 = *(const ulonglong2*)&Au[buf][kk][tr * 2];
            fma2(acc[0][0], wv.x, a2.x); fma2(acc[0][1], wv.y, a2.x);
            fma2(acc[1][0], wv.x, a2.y); fma2(acc[1][1], wv.y, a2.y);
        }
        buf ^= 1;
    }
    int r0 = tr * 2;
#pragma unroll
    for (int cp = 0; cp < 2; cp++) {
        int c = cb + cg * 4 + 2 * cp;
        float2 bv = *(const float2*)&bias[c];
        float2 v0 = upk(acc[0][cp]);
        float2 v1 = upk(acc[1][cp]);
        v0.x += bv.x; v0.y += bv.y;
        v1.x += bv.x; v1.y += bv.y;
        *(float2*)&out[((size_t)(r0 * LL + t)) * VV + c]       = v0;
        *(float2*)&out[((size_t)((r0 + 1) * LL + t)) * VV + c] = v1;
    }
}

// ---------------- reduce 2 partials (+bias/+Xenc) + LSTM cell (float4) -----
// grid 64, block 128: 8192 threads x 4 cells.
__global__ __launch_bounds__(128) void k_lstm_reduce(
    const float* __restrict__ bias, int use_xadd, int t, int store_enc)
{
    int i4 = blockIdx.x * 128 + threadIdx.x;    // 0..8191
    int base = i4 * 4;
    int b = base >> 10, d = base & 1023;
    const float4* xadd = (const float4*)(g_Xenc + (size_t)t * BB * G4);
    float4 gv[4];
#pragma unroll
    for (int g = 0; g < 4; g++) {
        int off4 = (b * G4 + g * DH + d) >> 2;
        float4 s = bias ? ((const float4*)bias)[(g * DH + d) >> 2]
                        : make_float4(0.f, 0.f, 0.f, 0.f);
        if (use_xadd) {
            float4 xv = xadd[off4];
            s.x += xv.x; s.y += xv.y; s.z += xv.z; s.w += xv.w;
        }
#pragma unroll
        for (int sp = 0; sp < 2; sp++) {
            float4 p = ((const float4*)g_part)[sp * (BB * G4 / 4) + off4];
            s.x += p.x; s.y += p.y; s.z += p.z; s.w += p.w;
        }
        gv[g] = s;
    }
    float4 cold = ((const float4*)g_c)[i4];
    float4 cn, hn;
    {
        float* iv = (float*)&gv[0]; float* fv = (float*)&gv[1];
        float* gg = (float*)&gv[2]; float* ov = (float*)&gv[3];
        float* cp = (float*)&cold; float* cnp = (float*)&cn; float* hnp = (float*)&hn;
#pragma unroll
        for (int j = 0; j < 4; j++) {
            float cc = sigm(fv[j]) * cp[j] + sigm(iv[j]) * tanhf(gg[j]);
            cnp[j] = cc;
            hnp[j] = sigm(ov[j]) * tanhf(cc);
        }
    }
    ((float4*)g_c)[i4] = cn;
    ((float4*)g_h)[i4] = hn;
    if (store_enc)
        ((float4*)g_enc_outs)[((b * LL + t) * DH + d) >> 2] = hn;
}

// ---------------- reduce 8 comb partials + bias + relu -> g_inp (float4) ---
// grid 64, block 128 (BB*DH/4 = 8192 float4s).
__global__ __launch_bounds__(128) void k_comb_reduce(const float* __restrict__ bias)
{
    int i4 = blockIdx.x * 128 + threadIdx.x;
    int d = (i4 * 4) & 1023;
    float4 s = ((const float4*)bias)[d >> 2];
#pragma unroll
    for (int sp = 0; sp < 8; sp++) {
        float4 p = ((const float4*)g_part)[sp * (BB * DH / 4) + i4];
        s.x += p.x; s.y += p.y; s.z += p.z; s.w += p.w;
    }
    s.x = fmaxf(s.x, 0.f); s.y = fmaxf(s.y, 0.f);
    s.z = fmaxf(s.z, 0.f); s.w = fmaxf(s.w, 0.f);
    ((float4*)g_inp)[i4] = s;
}

// ---------------- attention: embed gather + scores + softmax + ctx ---------
// grid 32 (one block per batch row), block 256.
__global__ __launch_bounds__(256) void k_attn(
    const float* __restrict__ dec_embed, const float* __restrict__ attn_w,
    const float* __restrict__ attn_b)
{
    int b = blockIdx.x, tid = threadIdx.x;
    __shared__ float se[DH], sh[DH], sc[LL], sp_[4][LL], red[128];
    int tok = g_tok[b];
    for (int k = tid; k < DH; k += 256) {
        float e = dec_embed[(size_t)tok * DH + k];
        se[k] = e;
        g_e[b * DH + k] = e;
        sh[k] = g_h[b * DH + k];
    }
    __syncthreads();

    // scores over L=64 (threads: 64 cols x 4 K-groups of 512), 8-way ILP
    int l = tid & 63, kg = tid >> 6;
    const float* src = (kg < 2) ? (se + kg * 512) : (sh + (kg - 2) * 512);
    const float* wbase = attn_w + (size_t)(kg * 512) * LL + l;
    float p0 = 0.f, p1 = 0.f, p2 = 0.f, p3 = 0.f;
    float p4 = 0.f, p5 = 0.f, p6 = 0.f, p7 = 0.f;
#pragma unroll 2
    for (int kk = 0; kk < 512; kk += 8) {
        p0 += src[kk + 0] * wbase[(size_t)(kk + 0) * LL];
        p1 += src[kk + 1] * wbase[(size_t)(kk + 1) * LL];
        p2 += src[kk + 2] * wbase[(size_t)(kk + 2) * LL];
        p3 += src[kk + 3] * wbase[(size_t)(kk + 3) * LL];
        p4 += src[kk + 4] * wbase[(size_t)(kk + 4) * LL];
        p5 += src[kk + 5] * wbase[(size_t)(kk + 5) * LL];
        p6 += src[kk + 6] * wbase[(size_t)(kk + 6) * LL];
        p7 += src[kk + 7] * wbase[(size_t)(kk + 7) * LL];
    }
    sp_[kg][l] = ((p0 + p1) + (p2 + p3)) + ((p4 + p5) + (p6 + p7));
    __syncthreads();
    if (tid < 64)
        sc[tid] = sp_[0][tid] + sp_[1][tid] + sp_[2][tid] + sp_[3][tid] + attn_b[tid];
    __syncthreads();

    // softmax over 64
    if (tid < 64) red[tid] = sc[tid];
    __syncthreads();
    for (int off = 32; off >= 1; off >>= 1) {
        if (tid < off) red[tid] = fmaxf(red[tid], red[tid + off]);
        __syncthreads();
    }
    float mx = red[0];
    __syncthreads();
    if (tid < 64) { float e = expf(sc[tid] - mx); sc[tid] = e; red[tid] = e; }
    __syncthreads();
    for (int off = 32; off >= 1; off >>= 1) {
        if (tid < off) red[tid] += red[tid + off];
        __syncthreads();
    }
    float inv = 1.f / red[0];
    __syncthreads();
    if (tid < 64) sc[tid] *= inv;
    __syncthreads();

    // ctx[d] = sum_l aw[l] * enc_outs[b][l][d]   (float4 over d)
    float4 acc4 = make_float4(0.f, 0.f, 0.f, 0.f);
    const float4* eob = (const float4*)(g_enc_outs + (size_t)b * LL * DH);
#pragma unroll 4
    for (int l2 = 0; l2 < LL; l2++) {
        float a = sc[l2];
        float4 e4 = eob[l2 * 256 + tid];
        acc4.x += a * e4.x; acc4.y += a * e4.y;
        acc4.z += a * e4.z; acc4.w += a * e4.w;
    }
    ((float4*)(g_ctx + b * DH))[tid] = acc4;
}

// ---------------- finalize A: per-chunk max/argmax + expsum (float4) -------
// grid (8, 32): chunk j (1000 float4s) of batch row b.
__global__ __launch_bounds__(256) void k_final_part(const float* __restrict__ out, int t)
{
    int j = blockIdx.x, b = blockIdx.y, tid = threadIdx.x;
    const float4* row4 = (const float4*)(out + ((size_t)(b * LL + t)) * VV) + j * 1000;
    int base_col = j * 4000;
    __shared__ float sm[256];
    __shared__ int si[256];

    float m = -1e30f; int mi = base_col;
    for (int i = tid; i < 1000; i += 256) {
        float4 v = row4[i];
        int c = base_col + i * 4;
        if (v.x > m) { m = v.x; mi = c; }
        if (v.y > m) { m = v.y; mi = c + 1; }
        if (v.z > m) { m = v.z; mi = c + 2; }
        if (v.w > m) { m = v.w; mi = c + 3; }
    }
    sm[tid] = m; si[tid] = mi;
    __syncthreads();
    for (int off = 128; off >= 1; off >>= 1) {
        if (tid < off) {
            float o = sm[tid + off]; int oi = si[tid + off];
            if (o > sm[tid] || (o == sm[tid] && oi < si[tid])) { sm[tid] = o; si[tid] = oi; }
        }
        __syncthreads();
    }
    float mx = sm[0]; int am = si[0];
    __syncthreads();

    float s = 0.f;
    for (int i = tid; i < 1000; i += 256) {
        float4 v = row4[i];
        s += expf(v.x - mx) + expf(v.y - mx) + expf(v.z - mx) + expf(v.w - mx);
    }
    sm[tid] = s;
    __syncthreads();
    for (int off = 128; off >= 1; off >>= 1) {
        if (tid < off) sm[tid] += sm[tid + off];
        __syncthreads();
    }
    if (tid == 0) {
        g_fm[b][j] = mx;
        g_fs[b][j] = sm[0];
        g_fi[b][j] = am;
    }
}

// ---------------- finalize B: merge partials, subtract lse, emit token -----
// grid (8, 32).
__global__ __launch_bounds__(256) void k_final_sub(float* __restrict__ out, int t)
{
    int j = blockIdx.x, b = blockIdx.y, tid = threadIdx.x;
    float M = -1e30f;
#pragma unroll
    for (int jj = 0; jj < 8; jj++) M = fmaxf(M, g_fm[b][jj]);
    float S = 0.f;
#pragma unroll
    for (int jj = 0; jj < 8; jj++) S += g_fs[b][jj] * expf(g_fm[b][jj] - M);
    float lse = M + logf(S);

    float4* row4 = (float4*)(out + ((size_t)(b * LL + t)) * VV) + j * 1000;
    for (int i = tid; i < 1000; i += 256) {
        float4 v = row4[i];
        v.x -= lse; v.y -= lse; v.z -= lse; v.w -= lse;
        row4[i] = v;
    }

    if (j == 0 && tid == 0) {
        float bm = -1e30f; int bi = 0;
#pragma unroll
        for (int jj = 0; jj < 8; jj++) {
            if (g_fm[b][jj] > bm) { bm = g_fm[b][jj]; bi = g_fi[b][jj]; }
        }
        g_tok[b] = bi;   // first-max-wins preserved by chunk order + strict >
    }
}

// ---------------- host launcher --------------------------------------------
extern "C" void kernel_launch(void* const* d_in, const int* in_sizes, int n_in,
                              void* d_out, int out_size)
{
    (void)in_sizes; (void)n_in; (void)out_size;
    const int*   x         = (const int*)  d_in[0];
    const float* enc_embed = (const float*)d_in[1];
    const float* enc_wx    = (const float*)d_in[2];
    const float* enc_wh    = (const float*)d_in[3];
    const float* enc_b     = (const float*)d_in[4];
    const float* dec_embed = (const float*)d_in[5];
    const float* attn_w    = (const float*)d_in[6];
    const float* attn_b    = (const float*)d_in[7];
    const float* comb_w    = (const float*)d_in[8];
    const float* comb_b    = (const float*)d_in[9];
    const float* dec_wx    = (const float*)d_in[10];
    const float* dec_wh    = (const float*)d_in[11];
    const float* dec_b     = (const float*)d_in[12];
    const float* out_w     = (const float*)d_in[13];
    const float* out_b     = (const float*)d_in[14];
    float* out = (float*)d_out;
    const int BIG = 1 << 30;

    // encoder
    k_init<<<128, 256>>>(0);
    k_enc_pre<<<dim3(32, 1, 64), 256>>>(x, enc_embed, enc_wx, enc_b);
    for (int t = 0; t < LL; t++) {
        // h @ enc_wh : K=1024 split 2 -> 128 blocks
        k_gemm_s<<<dim3(64, 2), 256>>>(0, enc_wh, enc_wh, BIG, G4, 512, G4);
        k_lstm_reduce<<<64, 128>>>(nullptr, 1, t, 1);
    }

    // decoder
    k_init<<<128, 256>>>(1);
    for (int t = 0; t < LL; t++) {
        k_attn<<<32, 256>>>(dec_embed, attn_w, attn_b);
        // cat(e,ctx) @ comb_w : K=2048 split 8 -> 128 blocks
        k_gemm_s<<<dim3(16, 8), 256>>>(1, comb_w, comb_w, BIG, DH, 256, DH);
        k_comb_reduce<<<64, 128>>>(comb_b);
        // inp@dec_wx + h@dec_wh : K=2048 split 2 -> 128 blocks
        k_gemm_s<<<dim3(64, 2), 256>>>(2, dec_wx, dec_wh, DH, G4, 1024, G4);
        k_lstm_reduce<<<64, 128>>>(dec_b, 0, t, 0);
        // logits + log_softmax + argmax feedback
        k_outproj<<<500, 256>>>(out_w, out_b, out, t);
        k_final_part<<<dim3(8, 32), 256>>>(out, t);
        k_final_sub<<<dim3(8, 32), 256>>>(out, t);
    }
}

// round 9
// speedup vs baseline: 2.2250x; 1.0847x over previous
#include <cuda_runtime.h>
#include <math.h>

// Problem constants
#define BB 32
#define LL 64
#define EE 512
#define DH 1024
#define G4 4096
#define VV 32000
#define MAXBLK 148

typedef unsigned long long ull;

// ---------------- scratch (device globals; no allocation allowed) ----------
__device__ __align__(16) float g_Xenc[LL * BB * G4];      // embed@enc_wx + enc_b
__device__ __align__(16) float g_enc_outs[BB * LL * DH];  // encoder hidden states
__device__ __align__(16) float g_part[8 * BB * G4];       // split-K partials
__device__ __align__(16) float g_h[BB * DH];
__device__ __align__(16) float g_c[BB * DH];
__device__ __align__(16) float g_e[BB * DH];
__device__ __align__(16) float g_ctx[BB * DH];
__device__ __align__(16) float g_inp[BB * DH];
__device__ int   g_tok[BB];
__device__ float g_fm[BB][8];
__device__ float g_fs[BB][8];
__device__ int   g_fi[BB][8];

// grid barrier state
__device__ unsigned g_cnt = 0;
__device__ volatile unsigned g_gen = 0;

// ---------------- f32x2 helpers (sm_103a packed FMA) -----------------------
__device__ __forceinline__ ull pk2(float w) {
    ull r; asm("mov.b64 %0, {%1, %1};" : "=l"(r) : "f"(w)); return r;
}
__device__ __forceinline__ void fma2(ull& d, ull a, ull b) {
    asm("fma.rn.f32x2 %0, %1, %2, %0;" : "+l"(d) : "l"(a), "l"(b));
}
__device__ __forceinline__ float2 upk(ull v) {
    float2 f; asm("mov.b64 {%0, %1}, %2;" : "=f"(f.x), "=f"(f.y) : "l"(v)); return f;
}
__device__ __forceinline__ float sigm(float x) { return 1.0f / (1.0f + expf(-x)); }

// ---------------- device-wide barrier (gridDim.x blocks, all resident) -----
__device__ __forceinline__ void gsync() {
    __threadfence();               // release: my writes visible at L2
    __syncthreads();
    if (threadIdx.x == 0) {
        unsigned gen = g_gen;
        if (atomicAdd(&g_cnt, 1u) == gridDim.x - 1) {
            atomicExch(&g_cnt, 0u);
            __threadfence();
            g_gen = gen + 1;
        } else {
            while (g_gen == gen) { __nanosleep(64); }
        }
        __threadfence();           // acquire: L1 invalidate before reads
    }
    __syncthreads();
}

// ---------------- one-time: Xenc[t] = embed(x[:,t]) @ enc_wx + enc_b -------
// grid (32, 1, 64), block 256. (standalone: massively parallel, one launch)
__global__ __launch_bounds__(256) void k_enc_pre(
    const int* __restrict__ x, const float* __restrict__ emb,
    const float* __restrict__ wx, const float* __restrict__ bias)
{
    __shared__ __align__(16) float As[32][34];
    int tid = threadIdx.x;
    int t = blockIdx.z;
    int txq = tid & 31, ty = tid >> 5;
    int c0 = blockIdx.x * 128 + txq * 4;
    int lb = tid >> 3, lk = (tid & 7) * 4;
    int tok = x[lb * LL + t];
    const float* arow = emb + (size_t)tok * EE;

    ull acc[4][2];
#pragma unroll
    for (int j = 0; j < 4; j++) { acc[j][0] = 0; acc[j][1] = 0; }

    for (int kc = 0; kc < EE; kc += 32) {
        __syncthreads();
        float4 v = *(const float4*)(arow + kc + lk);
        As[lk + 0][lb] = v.x; As[lk + 1][lb] = v.y;
        As[lk + 2][lb] = v.z; As[lk + 3][lb] = v.w;
        __syncthreads();
#pragma unroll 8
        for (int kk = 0; kk < 32; kk++) {
            float4 w4 = *(const float4*)(wx + (size_t)(kc + kk) * G4 + c0);
            ull wp0 = pk2(w4.x), wp1 = pk2(w4.y), wp2 = pk2(w4.z), wp3 = pk2(w4.w);
            ull a0 = *(const ull*)&As[kk][ty * 4];
            ull a1 = *(const ull*)&As[kk][ty * 4 + 2];
            fma2(acc[0][0], a0, wp0); fma2(acc[0][1], a1, wp0);
            fma2(acc[1][0], a0, wp1); fma2(acc[1][1], a1, wp1);
            fma2(acc[2][0], a0, wp2); fma2(acc[2][1], a1, wp2);
            fma2(acc[3][0], a0, wp3); fma2(acc[3][1], a1, wp3);
        }
    }
    float4 bv = *(const float4*)(bias + c0);
    float bj[4] = {bv.x, bv.y, bv.z, bv.w};
    float* outt = g_Xenc + (size_t)t * BB * G4;
#pragma unroll
    for (int j = 0; j < 4; j++) {
        int c = c0 + j;
#pragma unroll
        for (int rp = 0; rp < 2; rp++) {
            float2 v = upk(acc[j][rp]);
            int row = ty * 4 + rp * 2;
            outt[row * G4 + c]       = v.x + bj[j];
            outt[(row + 1) * G4 + c] = v.y + bj[j];
        }
    }
}

// ---------------- GEMM tile (64 cols x 32 rows), double buffered -----------
__device__ __forceinline__ void gemm64(
    const float* __restrict__ Ab, const float* __restrict__ Wb,
    int ldW, int KC, float* __restrict__ outp, int Nout, int cb, char* SM)
{
    float (*Ws)[32][64] = (float(*)[32][64])SM;
    ull   (*Au)[32][34] = (ull(*)[32][34])(SM + 16384);
    int tid = threadIdx.x;
    int cg = tid & 15, tr = tid >> 4;
    int wr0 = tid >> 4, wc0 = (tid & 15) * 4;
    int lb = tid >> 3, lk = (tid & 7) * 4;

    float4 w0 = *(const float4*)(Wb + (size_t)wr0 * ldW + cb + wc0);
    float4 w1 = *(const float4*)(Wb + (size_t)(wr0 + 16) * ldW + cb + wc0);
    float4 av = *(const float4*)(Ab + lb * DH + lk);

    ull acc[2][2] = {{0, 0}, {0, 0}};
    int buf = 0;
    for (int kc = 0; kc < KC; kc += 32) {
        *(float4*)&Ws[buf][wr0][wc0]      = w0;
        *(float4*)&Ws[buf][wr0 + 16][wc0] = w1;
        Au[buf][lk + 0][lb] = pk2(av.x);
        Au[buf][lk + 1][lb] = pk2(av.y);
        Au[buf][lk + 2][lb] = pk2(av.z);
        Au[buf][lk + 3][lb] = pk2(av.w);
        __syncthreads();
        if (kc + 32 < KC) {
            const float* wp = Wb + (size_t)(kc + 32) * ldW;
            w0 = *(const float4*)(wp + (size_t)wr0 * ldW + cb + wc0);
            w1 = *(const float4*)(wp + (size_t)(wr0 + 16) * ldW + cb + wc0);
            av = *(const float4*)(Ab + lb * DH + kc + 32 + lk);
        }
#pragma unroll
        for (int kk = 0; kk < 32; kk++) {
            ulonglong2 wv = *(const ulonglong2*)&Ws[buf][kk][cg * 4];
            ulonglong2 a2 = *(const ulonglong2*)&Au[buf][kk][tr * 2];
            fma2(acc[0][0], wv.x, a2.x); fma2(acc[0][1], wv.y, a2.x);
            fma2(acc[1][0], wv.x, a2.y); fma2(acc[1][1], wv.y, a2.y);
        }
        buf ^= 1;
    }
    __syncthreads();
    int r0 = tr * 2;
#pragma unroll
    for (int cp = 0; cp < 2; cp++) {
        int c = cb + cg * 4 + 2 * cp;
        float2 v0 = upk(acc[0][cp]);
        float2 v1 = upk(acc[1][cp]);
        *(float2*)&outp[(size_t)r0 * Nout + c]       = v0;
        *(float2*)&outp[(size_t)(r0 + 1) * Nout + c] = v1;
    }
}

// ---------------- outproj tile (128 cols x 32 rows), K=1024 ----------------
__device__ __forceinline__ void outproj_tile(
    const float* __restrict__ w, const float* __restrict__ bias,
    float* __restrict__ out, int t, int cb, char* SM)
{
    float4 (*Wsp)[32][32] = (float4(*)[32][32])SM;            // [buf][row][f4]
    float  (*Af)[32][36]  = (float(*)[32][36])(SM + 32768);
    int tid = threadIdx.x;
    int cq = tid & 31, rg = tid >> 5;
    int wrow = tid >> 3, wf4 = (tid & 7) * 4;
    int lb = tid >> 3, lk = (tid & 7) * 4;

    const float4* wbase = (const float4*)(w + (size_t)wrow * VV + cb) + wf4;
    float4 wld[4];
#pragma unroll
    for (int i = 0; i < 4; i++) wld[i] = __ldcs(wbase + i);
    float4 av = *(const float4*)(g_h + lb * DH + lk);

    ull acc[2][4];
#pragma unroll
    for (int cp = 0; cp < 2; cp++)
#pragma unroll
        for (int r = 0; r < 4; r++) acc[cp][r] = 0;

    int buf = 0;
    for (int kc = 0; kc < DH; kc += 32) {
#pragma unroll
        for (int i = 0; i < 4; i++) Wsp[buf][wrow][wf4 + i] = wld[i];
        Af[buf][lk + 0][lb] = av.x; Af[buf][lk + 1][lb] = av.y;
        Af[buf][lk + 2][lb] = av.z; Af[buf][lk + 3][lb] = av.w;
        __syncthreads();
        if (kc + 32 < DH) {
            const float4* wn = (const float4*)(w + (size_t)(kc + 32 + wrow) * VV + cb) + wf4;
#pragma unroll
            for (int i = 0; i < 4; i++) wld[i] = __ldcs(wn + i);
            av = *(const float4*)(g_h + lb * DH + kc + 32 + lk);
        }
#pragma unroll
        for (int kk = 0; kk < 32; kk++) {
            float4 w4 = Wsp[buf][kk][cq];
            ulonglong2 wv = *(ulonglong2*)&w4;
            float4 a4 = *(const float4*)&Af[buf][kk][rg * 4];
            ull a0 = pk2(a4.x), a1 = pk2(a4.y), a2 = pk2(a4.z), a3 = pk2(a4.w);
            fma2(acc[0][0], wv.x, a0); fma2(acc[1][0], wv.y, a0);
            fma2(acc[0][1], wv.x, a1); fma2(acc[1][1], wv.y, a1);
            fma2(acc[0][2], wv.x, a2); fma2(acc[1][2], wv.y, a2);
            fma2(acc[0][3], wv.x, a3); fma2(acc[1][3], wv.y, a3);
        }
        buf ^= 1;
    }
    __syncthreads();
#pragma unroll
    for (int cp = 0; cp < 2; cp++) {
        int c = cb + cq * 4 + cp * 2;
        float2 bv = *(const float2*)&bias[c];
#pragma unroll
        for (int r = 0; r < 4; r++) {
            float2 v = upk(acc[cp][r]);
            v.x += bv.x; v.y += bv.y;
            int row = rg * 4 + r;
            *(float2*)&out[((size_t)(row * LL + t)) * VV + c] = v;
        }
    }
}

// ---------------- fused epilogues (inline phases) ---------------------------
__device__ __forceinline__ void lstm_reduce_unit(
    int gid, const float* bias, int use_xadd, int t, int store_enc)
{
    int base = gid * 4;
    int b = base >> 10, d = base & 1023;
    const float4* xadd = (const float4*)(g_Xenc + (size_t)t * BB * G4);
    float4 gv[4];
#pragma unroll
    for (int g = 0; g < 4; g++) {
        int off4 = (b * G4 + g * DH + d) >> 2;
        float4 s = bias ? ((const float4*)bias)[(g * DH + d) >> 2]
                        : make_float4(0.f, 0.f, 0.f, 0.f);
        if (use_xadd) {
            float4 xv = xadd[off4];
            s.x += xv.x; s.y += xv.y; s.z += xv.z; s.w += xv.w;
        }
#pragma unroll
        for (int sp = 0; sp < 2; sp++) {
            float4 p = ((const float4*)g_part)[sp * (BB * G4 / 4) + off4];
            s.x += p.x; s.y += p.y; s.z += p.z; s.w += p.w;
        }
        gv[g] = s;
    }
    float4 cold = ((const float4*)g_c)[gid];
    float4 cn, hn;
    {
        float* iv = (float*)&gv[0]; float* fv = (float*)&gv[1];
        float* gg = (float*)&gv[2]; float* ov = (float*)&gv[3];
        float* cp = (float*)&cold; float* cnp = (float*)&cn; float* hnp = (float*)&hn;
#pragma unroll
        for (int j = 0; j < 4; j++) {
            float cc = sigm(fv[j]) * cp[j] + sigm(iv[j]) * tanhf(gg[j]);
            cnp[j] = cc;
            hnp[j] = sigm(ov[j]) * tanhf(cc);
        }
    }
    ((float4*)g_c)[gid] = cn;
    ((float4*)g_h)[gid] = hn;
    if (store_enc)
        ((float4*)g_enc_outs)[((b * LL + t) * DH + d) >> 2] = hn;
}

// ---------------- THE persistent kernel ------------------------------------
__global__ __launch_bounds__(256) void k_persist(
    const float* __restrict__ enc_wh,
    const float* __restrict__ dec_embed, const float* __restrict__ attn_w,
    const float* __restrict__ attn_b,
    const float* __restrict__ comb_w, const float* __restrict__ comb_b,
    const float* __restrict__ dec_wx, const float* __restrict__ dec_wh,
    const float* __restrict__ dec_b,
    const float* __restrict__ out_w, const float* __restrict__ out_b,
    float* __restrict__ out)
{
    __shared__ __align__(16) char SM[41984];
    int bx = blockIdx.x, tid = threadIdx.x;
    int nb = gridDim.x;
    int nthr = nb * 256;
    int gid0 = bx * 256 + tid;

    // ---- init h=c=0 ----
    for (int u = gid0; u < BB * DH / 4; u += nthr) {
        ((float4*)g_h)[u] = make_float4(0.f, 0.f, 0.f, 0.f);
        ((float4*)g_c)[u] = make_float4(0.f, 0.f, 0.f, 0.f);
    }
    gsync();

    // ================= encoder: 64 steps =================
    for (int t = 0; t < LL; t++) {
        for (int u = bx; u < 128; u += nb) {
            int ct = u & 63, sp = u >> 6;       // 64 tiles x 2 splits (KC=512)
            int k0 = sp * 512;
            gemm64(g_h + k0, enc_wh + (size_t)k0 * G4, G4, 512,
                   g_part + (size_t)sp * BB * G4, G4, ct * 64, SM);
            __syncthreads();
        }
        gsync();
        for (int u = gid0; u < BB * DH / 4; u += nthr)
            lstm_reduce_unit(u, nullptr, 1, t, 1);
        gsync();
    }

    // ---- decoder init ----
    for (int u = gid0; u < BB * DH / 4; u += nthr) {
        ((float4*)g_h)[u] = make_float4(0.f, 0.f, 0.f, 0.f);
        ((float4*)g_c)[u] = make_float4(0.f, 0.f, 0.f, 0.f);
    }
    if (gid0 < BB) g_tok[gid0] = 127;
    gsync();

    // ================= decoder: 64 steps =================
    for (int t = 0; t < LL; t++) {
        // ---- P1: attention (32 units, one per batch row) ----
        for (int b = bx; b < BB; b += nb) {
            float* se  = (float*)SM;
            float* sh  = se + DH;
            float* sc  = sh + DH;
            float* sp4 = sc + 64;
            float* red = sp4 + 256;
            int tok = g_tok[b];
            for (int k = tid; k < DH; k += 256) {
                float e = dec_embed[(size_t)tok * DH + k];
                se[k] = e;
                g_e[b * DH + k] = e;
                sh[k] = g_h[b * DH + k];
            }
            __syncthreads();
            int l = tid & 63, kg = tid >> 6;
            const float* src = (kg < 2) ? (se + kg * 512) : (sh + (kg - 2) * 512);
            const float* wbase = attn_w + (size_t)(kg * 512) * LL + l;
            float p0 = 0.f, p1 = 0.f, p2 = 0.f, p3 = 0.f;
            float p4 = 0.f, p5 = 0.f, p6 = 0.f, p7 = 0.f;
#pragma unroll 2
            for (int kk = 0; kk < 512; kk += 8) {
                p0 += src[kk + 0] * wbase[(size_t)(kk + 0) * LL];
                p1 += src[kk + 1] * wbase[(size_t)(kk + 1) * LL];
                p2 += src[kk + 2] * wbase[(size_t)(kk + 2) * LL];
                p3 += src[kk + 3] * wbase[(size_t)(kk + 3) * LL];
                p4 += src[kk + 4] * wbase[(size_t)(kk + 4) * LL];
                p5 += src[kk + 5] * wbase[(size_t)(kk + 5) * LL];
                p6 += src[kk + 6] * wbase[(size_t)(kk + 6) * LL];
                p7 += src[kk + 7] * wbase[(size_t)(kk + 7) * LL];
            }
            sp4[kg * 64 + l] = ((p0 + p1) + (p2 + p3)) + ((p4 + p5) + (p6 + p7));
            __syncthreads();
            if (tid < 64)
                sc[tid] = sp4[tid] + sp4[64 + tid] + sp4[128 + tid] + sp4[192 + tid]
                        + attn_b[tid];
            __syncthreads();
            if (tid < 64) red[tid] = sc[tid];
            __syncthreads();
            for (int off = 32; off >= 1; off >>= 1) {
                if (tid < off) red[tid] = fmaxf(red[tid], red[tid + off]);
                __syncthreads();
            }
            float mx = red[0];
            __syncthreads();
            if (tid < 64) { float e = expf(sc[tid] - mx); sc[tid] = e; red[tid] = e; }
            __syncthreads();
            for (int off = 32; off >= 1; off >>= 1) {
                if (tid < off) red[tid] += red[tid + off];
                __syncthreads();
            }
            float inv = 1.f / red[0];
            __syncthreads();
            if (tid < 64) sc[tid] *= inv;
            __syncthreads();
            float4 acc4 = make_float4(0.f, 0.f, 0.f, 0.f);
            const float4* eob = (const float4*)(g_enc_outs + (size_t)b * LL * DH);
#pragma unroll 4
            for (int l2 = 0; l2 < LL; l2++) {
                float a = sc[l2];
                float4 e4 = eob[l2 * 256 + tid];
                acc4.x += a * e4.x; acc4.y += a * e4.y;
                acc4.z += a * e4.z; acc4.w += a * e4.w;
            }
            ((float4*)(g_ctx + b * DH))[tid] = acc4;
            __syncthreads();
        }
        gsync();

        // ---- P2: comb gemm (16 tiles x 8 splits, KC=256) ----
        for (int u = bx; u < 128; u += nb) {
            int ct = u & 15, sp = u >> 4;
            int k0 = sp * 256;
            const float* Ab = (k0 < DH) ? (g_e + k0) : (g_ctx + k0 - DH);
            gemm64(Ab, comb_w + (size_t)k0 * DH, DH, 256,
                   g_part + (size_t)sp * BB * DH, DH, ct * 64, SM);
            __syncthreads();
        }
        gsync();

        // ---- P3: comb reduce + relu ----
        for (int u = gid0; u < BB * DH / 4; u += nthr) {
            int d = (u * 4) & 1023;
            float4 s = ((const float4*)comb_b)[d >> 2];
#pragma unroll
            for (int sp = 0; sp < 8; sp++) {
                float4 p = ((const float4*)g_part)[sp * (BB * DH / 4) + u];
                s.x += p.x; s.y += p.y; s.z += p.z; s.w += p.w;
            }
            s.x = fmaxf(s.x, 0.f); s.y = fmaxf(s.y, 0.f);
            s.z = fmaxf(s.z, 0.f); s.w = fmaxf(s.w, 0.f);
            ((float4*)g_inp)[u] = s;
        }
        gsync();

        // ---- P4: gates gemm (64 tiles x 2 splits, KC=1024) ----
        for (int u = bx; u < 128; u += nb) {
            int ct = u & 63, sp = u >> 6;
            const float* Ab = sp ? g_h : g_inp;
            const float* Wb = sp ? dec_wh : dec_wx;
            gemm64(Ab, Wb, G4, 1024,
                   g_part + (size_t)sp * BB * G4, G4, ct * 64, SM);
            __syncthreads();
        }
        gsync();

        // ---- P5: LSTM reduce ----
        for (int u = gid0; u < BB * DH / 4; u += nthr)
            lstm_reduce_unit(u, dec_b, 0, t, 0);
        gsync();

        // ---- P6: output projection (250 tiles of 128 cols) ----
        for (int u = bx; u < 250; u += nb) {
            outproj_tile(out_w, out_b, out, t, u * 128, SM);
            __syncthreads();
        }
        gsync();

        // ---- P7: final part (256 units: 8 chunks x 32 rows) ----
        for (int u = bx; u < 256; u += nb) {
            int j = u & 7, b = u >> 3;
            const float4* row4 = (const float4*)(out + ((size_t)(b * LL + t)) * VV)
                               + j * 1000;
            int base_col = j * 4000;
            float* smf = (float*)SM;
            int*   sif = (int*)(SM + 1024);
            float m = -1e30f; int mi = base_col;
            for (int i = tid; i < 1000; i += 256) {
                float4 v = row4[i];
                int c = base_col + i * 4;
                if (v.x > m) { m = v.x; mi = c; }
                if (v.y > m) { m = v.y; mi = c + 1; }
                if (v.z > m) { m = v.z; mi = c + 2; }
                if (v.w > m) { m = v.w; mi = c + 3; }
            }
            smf[tid] = m; sif[tid] = mi;
            __syncthreads();
            for (int off = 128; off >= 1; off >>= 1) {
                if (tid < off) {
                    float o = smf[tid + off]; int oi = sif[tid + off];
                    if (o > smf[tid] || (o == smf[tid] && oi < sif[tid])) {
                        smf[tid] = o; sif[tid] = oi;
                    }
                }
                __syncthreads();
            }
            float mx = smf[0]; int am = sif[0];
            __syncthreads();
            float s = 0.f;
            for (int i = tid; i < 1000; i += 256) {
                float4 v = row4[i];
                s += expf(v.x - mx) + expf(v.y - mx) + expf(v.z - mx) + expf(v.w - mx);
            }
            smf[tid] = s;
            __syncthreads();
            for (int off = 128; off >= 1; off >>= 1) {
                if (tid < off) smf[tid] += smf[tid + off];
                __syncthreads();
            }
            if (tid == 0) {
                g_fm[b][j] = mx;
                g_fs[b][j] = smf[0];
                g_fi[b][j] = am;
            }
            __syncthreads();
        }
        gsync();

        // ---- P8: final sub + token ----
        for (int u = bx; u < 256; u += nb) {
            int j = u & 7, b = u >> 3;
            float M = -1e30f;
#pragma unroll
            for (int jj = 0; jj < 8; jj++) M = fmaxf(M, g_fm[b][jj]);
            float S = 0.f;
#pragma unroll
            for (int jj = 0; jj < 8; jj++) S += g_fs[b][jj] * expf(g_fm[b][jj] - M);
            float lse = M + logf(S);
            float4* row4 = (float4*)(out + ((size_t)(b * LL + t)) * VV) + j * 1000;
            for (int i = tid; i < 1000; i += 256) {
                float4 v = row4[i];
                v.x -= lse; v.y -= lse; v.z -= lse; v.w -= lse;
                row4[i] = v;
            }
            if (j == 0 && tid == 0) {
                float bm = -1e30f; int bi = 0;
#pragma unroll
                for (int jj = 0; jj < 8; jj++) {
                    if (g_fm[b][jj] > bm) { bm = g_fm[b][jj]; bi = g_fi[b][jj]; }
                }
                g_tok[b] = bi;
            }
        }
        gsync();
    }
}

// ---------------- host launcher --------------------------------------------
extern "C" void kernel_launch(void* const* d_in, const int* in_sizes, int n_in,
                              void* d_out, int out_size)
{
    (void)in_sizes; (void)n_in; (void)out_size;
    const int*   x         = (const int*)  d_in[0];
    const float* enc_embed = (const float*)d_in[1];
    const float* enc_wx    = (const float*)d_in[2];
    const float* enc_wh    = (const float*)d_in[3];
    const float* enc_b     = (const float*)d_in[4];
    const float* dec_embed = (const float*)d_in[5];
    const float* attn_w    = (const float*)d_in[6];
    const float* attn_b    = (const float*)d_in[7];
    const float* comb_w    = (const float*)d_in[8];
    const float* comb_b    = (const float*)d_in[9];
    const float* dec_wx    = (const float*)d_in[10];
    const float* dec_wh    = (const float*)d_in[11];
    const float* dec_b     = (const float*)d_in[12];
    const float* out_w     = (const float*)d_in[13];
    const float* out_b     = (const float*)d_in[14];
    float* out = (float*)d_out;

    // Grid must not exceed co-resident capacity: 1 block/SM guaranteed
    // (256 thr, 41KB smem). Query actual SM count to avoid spin-barrier
    // deadlock on partitioned/odd-SM-count devices.
    int dev = 0, nsm = MAXBLK;
    cudaGetDevice(&dev);
    cudaDeviceGetAttribute(&nsm, cudaDevAttrMultiProcessorCount, dev);
    int nblk = nsm < MAXBLK ? nsm : MAXBLK;

    k_enc_pre<<<dim3(32, 1, 64), 256>>>(x, enc_embed, enc_wx, enc_b);
    k_persist<<<nblk, 256>>>(enc_wh, dec_embed, attn_w, attn_b,
                             comb_w, comb_b, dec_wx, dec_wh, dec_b,
                             out_w, out_b, out);
}

// round 10
// speedup vs baseline: 2.3964x; 1.0770x over previous
#include <cuda_runtime.h>
#include <math.h>

// Problem constants
#define BB 32
#define LL 64
#define EE 512
#define DH 1024
#define G4 4096
#define VV 32000
#define MAXBLK 148
#define NTILES_OP 125   // 32000 / 256

typedef unsigned long long ull;

// ---------------- scratch (device globals; no allocation allowed) ----------
__device__ __align__(16) float g_Xenc[LL * BB * G4];      // embed@enc_wx + enc_b
__device__ __align__(16) float g_enc_outs[BB * LL * DH];  // encoder hidden states
__device__ __align__(16) float g_part[8 * BB * G4];       // split-K partials
__device__ __align__(16) float g_h[BB * DH];
__device__ __align__(16) float g_c[BB * DH];
__device__ __align__(16) float g_e[BB * DH];
__device__ __align__(16) float g_ctx[BB * DH];
__device__ __align__(16) float g_inp[BB * DH];
__device__ int   g_tok[BB];
__device__ float g_pm[BB][128];   // per-outproj-tile max
__device__ float g_ps[BB][128];   // per-outproj-tile sum exp(x - tilemax)
__device__ int   g_pi[BB][128];   // per-outproj-tile argmax

// grid barrier state
__device__ unsigned g_cnt = 0;
__device__ volatile unsigned g_gen = 0;

// ---------------- f32x2 helpers (sm_103a packed FMA) -----------------------
__device__ __forceinline__ ull pk2(float w) {
    ull r; asm("mov.b64 %0, {%1, %1};" : "=l"(r) : "f"(w)); return r;
}
__device__ __forceinline__ void fma2(ull& d, ull a, ull b) {
    asm("fma.rn.f32x2 %0, %1, %2, %0;" : "+l"(d) : "l"(a), "l"(b));
}
__device__ __forceinline__ float2 upk(ull v) {
    float2 f; asm("mov.b64 {%0, %1}, %2;" : "=f"(f.x), "=f"(f.y) : "l"(v)); return f;
}
__device__ __forceinline__ float sigm(float x) { return 1.0f / (1.0f + expf(-x)); }

// ---------------- device-wide barrier (gridDim.x blocks, all resident) -----
__device__ __forceinline__ void gsync() {
    __threadfence();               // release
    __syncthreads();
    if (threadIdx.x == 0) {
        unsigned gen = g_gen;
        if (atomicAdd(&g_cnt, 1u) == gridDim.x - 1) {
            atomicExch(&g_cnt, 0u);
            __threadfence();
            g_gen = gen + 1;
        } else {
            while (g_gen == gen) { __nanosleep(64); }
        }
        __threadfence();           // acquire (CCTL.IVALL -> fresh L1)
    }
    __syncthreads();
}

// ---------------- one-time: Xenc[t] = embed(x[:,t]) @ enc_wx + enc_b -------
__global__ __launch_bounds__(256) void k_enc_pre(
    const int* __restrict__ x, const float* __restrict__ emb,
    const float* __restrict__ wx, const float* __restrict__ bias)
{
    __shared__ __align__(16) float As[32][34];
    int tid = threadIdx.x;
    int t = blockIdx.z;
    int txq = tid & 31, ty = tid >> 5;
    int c0 = blockIdx.x * 128 + txq * 4;
    int lb = tid >> 3, lk = (tid & 7) * 4;
    int tok = x[lb * LL + t];
    const float* arow = emb + (size_t)tok * EE;

    ull acc[4][2];
#pragma unroll
    for (int j = 0; j < 4; j++) { acc[j][0] = 0; acc[j][1] = 0; }

    for (int kc = 0; kc < EE; kc += 32) {
        __syncthreads();
        float4 v = *(const float4*)(arow + kc + lk);
        As[lk + 0][lb] = v.x; As[lk + 1][lb] = v.y;
        As[lk + 2][lb] = v.z; As[lk + 3][lb] = v.w;
        __syncthreads();
#pragma unroll 8
        for (int kk = 0; kk < 32; kk++) {
            float4 w4 = *(const float4*)(wx + (size_t)(kc + kk) * G4 + c0);
            ull wp0 = pk2(w4.x), wp1 = pk2(w4.y), wp2 = pk2(w4.z), wp3 = pk2(w4.w);
            ull a0 = *(const ull*)&As[kk][ty * 4];
            ull a1 = *(const ull*)&As[kk][ty * 4 + 2];
            fma2(acc[0][0], a0, wp0); fma2(acc[0][1], a1, wp0);
            fma2(acc[1][0], a0, wp1); fma2(acc[1][1], a1, wp1);
            fma2(acc[2][0], a0, wp2); fma2(acc[2][1], a1, wp2);
            fma2(acc[3][0], a0, wp3); fma2(acc[3][1], a1, wp3);
        }
    }
    float4 bv = *(const float4*)(bias + c0);
    float bj[4] = {bv.x, bv.y, bv.z, bv.w};
    float* outt = g_Xenc + (size_t)t * BB * G4;
#pragma unroll
    for (int j = 0; j < 4; j++) {
        int c = c0 + j;
#pragma unroll
        for (int rp = 0; rp < 2; rp++) {
            float2 v = upk(acc[j][rp]);
            int row = ty * 4 + rp * 2;
            outt[row * G4 + c]       = v.x + bj[j];
            outt[(row + 1) * G4 + c] = v.y + bj[j];
        }
    }
}

// ============ 256-col x 32-row GEMM core, KSTEP=16, double buffered ========
// Thread = 8 consecutive cols (4 col-pairs) x 4 rows. 16 FMA2 per kk.
// Ws: float[2][16][256] @SM (32KB). Au: ull[2][16][34] @SM+32768 (8.7KB).
// Accumulators packed over COLUMNS (colpair), A broadcast packed in smem.
#define G256_LOOP(ACCBODY)                                                    \
    float (*Ws)[16][256] = (float(*)[16][256])SM;                             \
    ull   (*Au)[16][34]  = (ull(*)[16][34])(SM + 32768);                      \
    int tid = threadIdx.x;                                                    \
    int cq = tid & 31, rg = tid >> 5;                                         \
    int wk = tid >> 6, wf = tid & 63;                                         \
    int ab = tid >> 2, aq = (tid & 3) * 4;                                    \
    float4 wld[4]; float4 av = make_float4(0.f, 0.f, 0.f, 0.f);               \
    _Pragma("unroll")                                                         \
    for (int p = 0; p < 4; p++)                                               \
        wld[p] = LDW(Wb + (size_t)(wk + p * 4) * ldW + cb + wf * 4);          \
    if (tid < 128) av = *(const float4*)(Ab + ab * DH + aq);                  \
    ull acc[4][4];                                                            \
    _Pragma("unroll")                                                         \
    for (int cp = 0; cp < 4; cp++)                                            \
        _Pragma("unroll")                                                     \
        for (int r = 0; r < 4; r++) acc[cp][r] = 0;                           \
    int buf = 0;                                                              \
    for (int kc = 0; kc < KC; kc += 16) {                                     \
        _Pragma("unroll")                                                     \
        for (int p = 0; p < 4; p++)                                           \
            *(float4*)&Ws[buf][wk + p * 4][wf * 4] = wld[p];                  \
        if (tid < 128) {                                                      \
            Au[buf][aq + 0][ab] = pk2(av.x);                                  \
            Au[buf][aq + 1][ab] = pk2(av.y);                                  \
            Au[buf][aq + 2][ab] = pk2(av.z);                                  \
            Au[buf][aq + 3][ab] = pk2(av.w);                                  \
        }                                                                     \
        __syncthreads();                                                      \
        if (kc + 16 < KC) {                                                   \
            const float* wn = Wb + (size_t)(kc + 16) * ldW;                   \
            _Pragma("unroll")                                                 \
            for (int p = 0; p < 4; p++)                                       \
                wld[p] = LDW(wn + (size_t)(wk + p * 4) * ldW + cb + wf * 4);  \
            if (tid < 128)                                                    \
                av = *(const float4*)(Ab + ab * DH + kc + 16 + aq);           \
        }                                                                     \
        _Pragma("unroll")                                                     \
        for (int kk = 0; kk < 16; kk++) {                                     \
            ulonglong2 wA = *(const ulonglong2*)&Ws[buf][kk][cq * 8];         \
            ulonglong2 wB = *(const ulonglong2*)&Ws[buf][kk][cq * 8 + 4];     \
            ulonglong2 aA = *(const ulonglong2*)&Au[buf][kk][rg * 4];         \
            ulonglong2 aB = *(const ulonglong2*)&Au[buf][kk][rg * 4 + 2];     \
            fma2(acc[0][0], wA.x, aA.x); fma2(acc[0][1], wA.x, aA.y);         \
            fma2(acc[0][2], wA.x, aB.x); fma2(acc[0][3], wA.x, aB.y);         \
            fma2(acc[1][0], wA.y, aA.x); fma2(acc[1][1], wA.y, aA.y);         \
            fma2(acc[1][2], wA.y, aB.x); fma2(acc[1][3], wA.y, aB.y);         \
            fma2(acc[2][0], wB.x, aA.x); fma2(acc[2][1], wB.x, aA.y);         \
            fma2(acc[2][2], wB.x, aB.x); fma2(acc[2][3], wB.x, aB.y);         \
            fma2(acc[3][0], wB.y, aA.x); fma2(acc[3][1], wB.y, aA.y);         \
            fma2(acc[3][2], wB.y, aB.x); fma2(acc[3][3], wB.y, aB.y);         \
        }                                                                     \
        buf ^= 1;                                                             \
    }                                                                         \
    __syncthreads();                                                          \
    ACCBODY

// partial-writing variant (encoder / gates)
__device__ __forceinline__ void gemm256(
    const float* __restrict__ Ab, const float* __restrict__ Wb,
    int ldW, int KC, float* __restrict__ outp, int Nout, int cb, char* SM)
{
#define LDW(p) (*(const float4*)(p))
    G256_LOOP({
#pragma unroll
        for (int cp = 0; cp < 4; cp++) {
            int c = cb + cq * 8 + cp * 2;
#pragma unroll
            for (int r = 0; r < 4; r++) {
                float2 v = upk(acc[cp][r]);
                *(float2*)&outp[(size_t)(rg * 4 + r) * Nout + c] = v;
            }
        }
    })
#undef LDW
}

// outproj variant: streams out_w, adds bias, writes logits, fused per-tile
// max/argmax/expsum via warp shfl (warp == one row-group of 4 rows).
__device__ __forceinline__ void outproj256(
    const float* __restrict__ Ab, const float* __restrict__ Wb,
    int ldW, int KC, const float* __restrict__ bias,
    float* __restrict__ out, int t, int tile, int cb, char* SM)
{
#define LDW(p) __ldcs((const float4*)(p))
    G256_LOOP({
        float barr[8];
#pragma unroll
        for (int cp = 0; cp < 4; cp++) {
            float2 bv = *(const float2*)&bias[cb + cq * 8 + cp * 2];
            barr[cp * 2] = bv.x; barr[cp * 2 + 1] = bv.y;
        }
#pragma unroll
        for (int r = 0; r < 4; r++) {
            int row = rg * 4 + r;
            float v[8];
#pragma unroll
            for (int cp = 0; cp < 4; cp++) {
                float2 x = upk(acc[cp][r]);
                v[cp * 2]     = x.x + barr[cp * 2];
                v[cp * 2 + 1] = x.y + barr[cp * 2 + 1];
            }
            float* orow = out + ((size_t)(row * LL + t)) * VV + cb + cq * 8;
#pragma unroll
            for (int cp = 0; cp < 4; cp++)
                *(float2*)&orow[cp * 2] = make_float2(v[cp * 2], v[cp * 2 + 1]);
            // local max/argmax (ascending col order -> first-max-wins)
            float m = v[0]; int mi = cb + cq * 8;
#pragma unroll
            for (int cc = 1; cc < 8; cc++)
                if (v[cc] > m) { m = v[cc]; mi = cb + cq * 8 + cc; }
            // warp xor-reduce (lattice max on (val, -idx))
#pragma unroll
            for (int o = 16; o >= 1; o >>= 1) {
                float om = __shfl_xor_sync(0xFFFFFFFFu, m, o);
                int   oi = __shfl_xor_sync(0xFFFFFFFFu, mi, o);
                if (om > m || (om == m && oi < mi)) { m = om; mi = oi; }
            }
            float s = 0.f;
#pragma unroll
            for (int cc = 0; cc < 8; cc++) s += __expf(v[cc] - m);
#pragma unroll
            for (int o = 16; o >= 1; o >>= 1)
                s += __shfl_xor_sync(0xFFFFFFFFu, s, o);
            if (cq == 0) {
                g_pm[row][tile] = m;
                g_ps[row][tile] = s;
                g_pi[row][tile] = mi;
            }
        }
    })
#undef LDW
}

// ---------------- 64-col GEMM core (comb only), KSTEP=32 -------------------
__device__ __forceinline__ void gemm64(
    const float* __restrict__ Ab, const float* __restrict__ Wb,
    int ldW, int KC, float* __restrict__ outp, int Nout, int cb, char* SM)
{
    float (*Ws)[32][64] = (float(*)[32][64])SM;
    ull   (*Au)[32][34] = (ull(*)[32][34])(SM + 16384);
    int tid = threadIdx.x;
    int cg = tid & 15, tr = tid >> 4;
    int wr0 = tid >> 4, wc0 = (tid & 15) * 4;
    int lb = tid >> 3, lk = (tid & 7) * 4;

    float4 w0 = *(const float4*)(Wb + (size_t)wr0 * ldW + cb + wc0);
    float4 w1 = *(const float4*)(Wb + (size_t)(wr0 + 16) * ldW + cb + wc0);
    float4 av = *(const float4*)(Ab + lb * DH + lk);

    ull acc[2][2] = {{0, 0}, {0, 0}};
    int buf = 0;
    for (int kc = 0; kc < KC; kc += 32) {
        *(float4*)&Ws[buf][wr0][wc0]      = w0;
        *(float4*)&Ws[buf][wr0 + 16][wc0] = w1;
        Au[buf][lk + 0][lb] = pk2(av.x);
        Au[buf][lk + 1][lb] = pk2(av.y);
        Au[buf][lk + 2][lb] = pk2(av.z);
        Au[buf][lk + 3][lb] = pk2(av.w);
        __syncthreads();
        if (kc + 32 < KC) {
            const float* wp = Wb + (size_t)(kc + 32) * ldW;
            w0 = *(const float4*)(wp + (size_t)wr0 * ldW + cb + wc0);
            w1 = *(const float4*)(wp + (size_t)(wr0 + 16) * ldW + cb + wc0);
            av = *(const float4*)(Ab + lb * DH + kc + 32 + lk);
        }
#pragma unroll
        for (int kk = 0; kk < 32; kk++) {
            ulonglong2 wv = *(const ulonglong2*)&Ws[buf][kk][cg * 4];
            ulonglong2 a2 = *(const ulonglong2*)&Au[buf][kk][tr * 2];
            fma2(acc[0][0], wv.x, a2.x); fma2(acc[0][1], wv.y, a2.x);
            fma2(acc[1][0], wv.x, a2.y); fma2(acc[1][1], wv.y, a2.y);
        }
        buf ^= 1;
    }
    __syncthreads();
    int r0 = tr * 2;
#pragma unroll
    for (int cp = 0; cp < 2; cp++) {
        int c = cb + cg * 4 + 2 * cp;
        float2 v0 = upk(acc[0][cp]);
        float2 v1 = upk(acc[1][cp]);
        *(float2*)&outp[(size_t)r0 * Nout + c]       = v0;
        *(float2*)&outp[(size_t)(r0 + 1) * Nout + c] = v1;
    }
}

// ---------------- LSTM reduce unit (8 split-K partials) --------------------
__device__ __forceinline__ void lstm_reduce_unit(
    int gid, const float* bias, int use_xadd, int t, int store_enc)
{
    int base = gid * 4;
    int b = base >> 10, d = base & 1023;
    const float4* xadd = (const float4*)(g_Xenc + (size_t)t * BB * G4);
    float4 gv[4];
#pragma unroll
    for (int g = 0; g < 4; g++) {
        int off4 = (b * G4 + g * DH + d) >> 2;
        float4 s = bias ? ((const float4*)bias)[(g * DH + d) >> 2]
                        : make_float4(0.f, 0.f, 0.f, 0.f);
        if (use_xadd) {
            float4 xv = xadd[off4];
            s.x += xv.x; s.y += xv.y; s.z += xv.z; s.w += xv.w;
        }
#pragma unroll
        for (int sp = 0; sp < 8; sp++) {
            float4 p = ((const float4*)g_part)[sp * (BB * G4 / 4) + off4];
            s.x += p.x; s.y += p.y; s.z += p.z; s.w += p.w;
        }
        gv[g] = s;
    }
    float4 cold = ((const float4*)g_c)[gid];
    float4 cn, hn;
    {
        float* iv = (float*)&gv[0]; float* fv = (float*)&gv[1];
        float* gg = (float*)&gv[2]; float* ov = (float*)&gv[3];
        float* cp = (float*)&cold; float* cnp = (float*)&cn; float* hnp = (float*)&hn;
#pragma unroll
        for (int j = 0; j < 4; j++) {
            float cc = sigm(fv[j]) * cp[j] + sigm(iv[j]) * tanhf(gg[j]);
            cnp[j] = cc;
            hnp[j] = sigm(ov[j]) * tanhf(cc);
        }
    }
    ((float4*)g_c)[gid] = cn;
    ((float4*)g_h)[gid] = hn;
    if (store_enc)
        ((float4*)g_enc_outs)[((b * LL + t) * DH + d) >> 2] = hn;
}

// ---------------- THE persistent kernel ------------------------------------
__global__ __launch_bounds__(256, 1) void k_persist(
    const float* __restrict__ enc_wh,
    const float* __restrict__ dec_embed, const float* __restrict__ attn_w,
    const float* __restrict__ attn_b,
    const float* __restrict__ comb_w, const float* __restrict__ comb_b,
    const float* __restrict__ dec_wx, const float* __restrict__ dec_wh,
    const float* __restrict__ dec_b,
    const float* __restrict__ out_w, const float* __restrict__ out_b,
    float* __restrict__ out)
{
    __shared__ __align__(16) char SM[41984];
    int bx = blockIdx.x, tid = threadIdx.x;
    int nb = gridDim.x;
    int nthr = nb * 256;
    int gid0 = bx * 256 + tid;

    // ---- init h=c=0 ----
    for (int u = gid0; u < BB * DH / 4; u += nthr) {
        ((float4*)g_h)[u] = make_float4(0.f, 0.f, 0.f, 0.f);
        ((float4*)g_c)[u] = make_float4(0.f, 0.f, 0.f, 0.f);
    }
    gsync();

    // ================= encoder: 64 steps =================
    for (int t = 0; t < LL; t++) {
        for (int u = bx; u < 128; u += nb) {      // 16 tiles x 8 splits (KC=128)
            int ct = u & 15, sp = u >> 4;
            int k0 = sp * 128;
            gemm256(g_h + k0, enc_wh + (size_t)k0 * G4, G4, 128,
                    g_part + (size_t)sp * BB * G4, G4, ct * 256, SM);
            __syncthreads();
        }
        gsync();
        for (int u = gid0; u < BB * DH / 4; u += nthr)
            lstm_reduce_unit(u, nullptr, 1, t, 1);
        gsync();
    }

    // ---- decoder init ----
    for (int u = gid0; u < BB * DH / 4; u += nthr) {
        ((float4*)g_h)[u] = make_float4(0.f, 0.f, 0.f, 0.f);
        ((float4*)g_c)[u] = make_float4(0.f, 0.f, 0.f, 0.f);
    }
    if (gid0 < BB) g_tok[gid0] = 127;
    gsync();

    // ================= decoder: 64 steps =================
    for (int t = 0; t < LL; t++) {
        // ---- P1: attention (32 units, one per batch row) ----
        for (int b = bx; b < BB; b += nb) {
            float* se  = (float*)SM;
            float* sh  = se + DH;
            float* sc  = sh + DH;
            float* sp4 = sc + 64;
            float* red = sp4 + 256;
            int tok = g_tok[b];
            for (int k = tid; k < DH; k += 256) {
                float e = dec_embed[(size_t)tok * DH + k];
                se[k] = e;
                g_e[b * DH + k] = e;
                sh[k] = g_h[b * DH + k];
            }
            __syncthreads();
            int l = tid & 63, kg = tid >> 6;
            const float* src = (kg < 2) ? (se + kg * 512) : (sh + (kg - 2) * 512);
            const float* wbase = attn_w + (size_t)(kg * 512) * LL + l;
            float p0 = 0.f, p1 = 0.f, p2 = 0.f, p3 = 0.f;
            float p4 = 0.f, p5 = 0.f, p6 = 0.f, p7 = 0.f;
#pragma unroll 2
            for (int kk = 0; kk < 512; kk += 8) {
                p0 += src[kk + 0] * wbase[(size_t)(kk + 0) * LL];
                p1 += src[kk + 1] * wbase[(size_t)(kk + 1) * LL];
                p2 += src[kk + 2] * wbase[(size_t)(kk + 2) * LL];
                p3 += src[kk + 3] * wbase[(size_t)(kk + 3) * LL];
                p4 += src[kk + 4] * wbase[(size_t)(kk + 4) * LL];
                p5 += src[kk + 5] * wbase[(size_t)(kk + 5) * LL];
                p6 += src[kk + 6] * wbase[(size_t)(kk + 6) * LL];
                p7 += src[kk + 7] * wbase[(size_t)(kk + 7) * LL];
            }
            sp4[kg * 64 + l] = ((p0 + p1) + (p2 + p3)) + ((p4 + p5) + (p6 + p7));
            __syncthreads();
            if (tid < 64)
                sc[tid] = sp4[tid] + sp4[64 + tid] + sp4[128 + tid] + sp4[192 + tid]
                        + attn_b[tid];
            __syncthreads();
            if (tid < 64) red[tid] = sc[tid];
            __syncthreads();
            for (int off = 32; off >= 1; off >>= 1) {
                if (tid < off) red[tid] = fmaxf(red[tid], red[tid + off]);
                __syncthreads();
            }
            float mx = red[0];
            __syncthreads();
            if (tid < 64) { float e = expf(sc[tid] - mx); sc[tid] = e; red[tid] = e; }
            __syncthreads();
            for (int off = 32; off >= 1; off >>= 1) {
                if (tid < off) red[tid] += red[tid + off];
                __syncthreads();
            }
            float inv = 1.f / red[0];
            __syncthreads();
            if (tid < 64) sc[tid] *= inv;
            __syncthreads();
            float4 acc4 = make_float4(0.f, 0.f, 0.f, 0.f);
            const float4* eob = (const float4*)(g_enc_outs + (size_t)b * LL * DH);
#pragma unroll 4
            for (int l2 = 0; l2 < LL; l2++) {
                float a = sc[l2];
                float4 e4 = eob[l2 * 256 + tid];
                acc4.x += a * e4.x; acc4.y += a * e4.y;
                acc4.z += a * e4.z; acc4.w += a * e4.w;
            }
            ((float4*)(g_ctx + b * DH))[tid] = acc4;
            __syncthreads();
        }
        gsync();

        // ---- P2: comb gemm (16 tiles x 8 splits, KC=256) ----
        for (int u = bx; u < 128; u += nb) {
            int ct = u & 15, sp = u >> 4;
            int k0 = sp * 256;
            const float* Ab = (k0 < DH) ? (g_e + k0) : (g_ctx + k0 - DH);
            gemm64(Ab, comb_w + (size_t)k0 * DH, DH, 256,
                   g_part + (size_t)sp * BB * DH, DH, ct * 64, SM);
            __syncthreads();
        }
        gsync();

        // ---- P3: comb reduce + relu ----
        for (int u = gid0; u < BB * DH / 4; u += nthr) {
            int d = (u * 4) & 1023;
            float4 s = ((const float4*)comb_b)[d >> 2];
#pragma unroll
            for (int sp = 0; sp < 8; sp++) {
                float4 p = ((const float4*)g_part)[sp * (BB * DH / 4) + u];
                s.x += p.x; s.y += p.y; s.z += p.z; s.w += p.w;
            }
            s.x = fmaxf(s.x, 0.f); s.y = fmaxf(s.y, 0.f);
            s.z = fmaxf(s.z, 0.f); s.w = fmaxf(s.w, 0.f);
            ((float4*)g_inp)[u] = s;
        }
        gsync();

        // ---- P4: gates gemm (16 tiles x 8 splits over K=2048, KC=256) ----
        for (int u = bx; u < 128; u += nb) {
            int ct = u & 15, sp = u >> 4;
            int k0 = sp * 256;
            const float* Ab = (k0 < DH) ? (g_inp + k0) : (g_h + k0 - DH);
            const float* Wb = (k0 < DH) ? (dec_wx + (size_t)k0 * G4)
                                        : (dec_wh + (size_t)(k0 - DH) * G4);
            gemm256(Ab, Wb, G4, 256,
                    g_part + (size_t)sp * BB * G4, G4, ct * 256, SM);
            __syncthreads();
        }
        gsync();

        // ---- P5: LSTM reduce ----
        for (int u = gid0; u < BB * DH / 4; u += nthr)
            lstm_reduce_unit(u, dec_b, 0, t, 0);
        gsync();

        // ---- P6: output projection + fused per-tile softmax stats ----
        for (int u = bx; u < NTILES_OP; u += nb) {
            outproj256(g_h, out_w, VV, DH, out_b, out, t, u, u * 256, SM);
            __syncthreads();
        }
        gsync();

        // ---- P7: merge tile stats, subtract lse, emit token ----
        for (int u = bx; u < 256; u += nb) {
            int j = u & 7, b = u >> 3;
            float M = -1e30f;
            for (int jj = 0; jj < NTILES_OP; jj++) M = fmaxf(M, g_pm[b][jj]);
            float S = 0.f;
            for (int jj = 0; jj < NTILES_OP; jj++)
                S += g_ps[b][jj] * __expf(g_pm[b][jj] - M);
            float lse = M + logf(S);
            float4* row4 = (float4*)(out + ((size_t)(b * LL + t)) * VV) + j * 1000;
            for (int i = tid; i < 1000; i += 256) {
                float4 v = row4[i];
                v.x -= lse; v.y -= lse; v.z -= lse; v.w -= lse;
                row4[i] = v;
            }
            if (j == 0 && tid == 0) {
                float bm = -1e30f; int bi = 0;
                for (int jj = 0; jj < NTILES_OP; jj++) {
                    if (g_pm[b][jj] > bm) { bm = g_pm[b][jj]; bi = g_pi[b][jj]; }
                }
                g_tok[b] = bi;   // tiles ascend in col; strict > keeps first max
            }
        }
        gsync();
    }
}

// ---------------- host launcher --------------------------------------------
extern "C" void kernel_launch(void* const* d_in, const int* in_sizes, int n_in,
                              void* d_out, int out_size)
{
    (void)in_sizes; (void)n_in; (void)out_size;
    const int*   x         = (const int*)  d_in[0];
    const float* enc_embed = (const float*)d_in[1];
    const float* enc_wx    = (const float*)d_in[2];
    const float* enc_wh    = (const float*)d_in[3];
    const float* enc_b     = (const float*)d_in[4];
    const float* dec_embed = (const float*)d_in[5];
    const float* attn_w    = (const float*)d_in[6];
    const float* attn_b    = (const float*)d_in[7];
    const float* comb_w    = (const float*)d_in[8];
    const float* comb_b    = (const float*)d_in[9];
    const float* dec_wx    = (const float*)d_in[10];
    const float* dec_wh    = (const float*)d_in[11];
    const float* dec_b     = (const float*)d_in[12];
    const float* out_w     = (const float*)d_in[13];
    const float* out_b     = (const float*)d_in[14];
    float* out = (float*)d_out;

    int dev = 0, nsm = MAXBLK;
    cudaGetDevice(&dev);
    cudaDeviceGetAttribute(&nsm, cudaDevAttrMultiProcessorCount, dev);
    int nblk = nsm < MAXBLK ? nsm : MAXBLK;

    k_enc_pre<<<dim3(32, 1, 64), 256>>>(x, enc_embed, enc_wx, enc_b);
    k_persist<<<nblk, 256>>>(enc_wh, dec_embed, attn_w, attn_b,
                             comb_w, comb_b, dec_wx, dec_wh, dec_b,
                             out_w, out_b, out);
}

// round 13
// speedup vs baseline: 2.9597x; 1.2351x over previous
#include <cuda_runtime.h>
#include <math.h>

// Problem constants
#define BB 32
#define LL 64
#define EE 512
#define DH 1024
#define G4 4096
#define VV 32000
#define MAXBLK 148
#define NTILES_OP 125   // 32000 / 256

typedef unsigned long long ull;

// ---------------- scratch (device globals; no allocation allowed) ----------
__device__ __align__(16) float g_Xenc[LL * BB * G4];      // embed@enc_wx + enc_b
__device__ __align__(16) float g_enc_outs[BB * LL * DH];  // encoder hidden states
__device__ __align__(16) float g_part[8 * BB * G4];       // split-K partials
__device__ __align__(16) float g_h[BB * DH];
__device__ __align__(16) float g_c[BB * DH];
__device__ __align__(16) float g_e[BB * DH];
__device__ __align__(16) float g_ctx[BB * DH];
__device__ __align__(16) float g_inp[BB * DH];
__device__ int   g_tok[BB];
__device__ float g_pm[BB][128];   // per-outproj-tile max
__device__ float g_ps[BB][128];   // per-outproj-tile sum exp(x - tilemax)
__device__ int   g_pi[BB][128];   // per-outproj-tile argmax

// grid barrier state
__device__ unsigned g_cnt = 0;
__device__ volatile unsigned g_gen = 0;

// ---------------- f32x2 helpers (sm_103a packed FMA) -----------------------
__device__ __forceinline__ ull pk2(float w) {
    ull r; asm("mov.b64 %0, {%1, %1};" : "=l"(r) : "f"(w)); return r;
}
__device__ __forceinline__ void fma2(ull& d, ull a, ull b) {
    asm("fma.rn.f32x2 %0, %1, %2, %0;" : "+l"(d) : "l"(a), "l"(b));
}
__device__ __forceinline__ float2 upk(ull v) {
    float2 f; asm("mov.b64 {%0, %1}, %2;" : "=f"(f.x), "=f"(f.y) : "l"(v)); return f;
}
__device__ __forceinline__ float sigm(float x) { return 1.0f / (1.0f + expf(-x)); }

// ---------------- device-wide barrier (gridDim.x blocks, all resident) -----
__device__ __forceinline__ void gsync() {
    __threadfence();               // release
    __syncthreads();
    if (threadIdx.x == 0) {
        unsigned gen = g_gen;
        if (atomicAdd(&g_cnt, 1u) == gridDim.x - 1) {
            atomicExch(&g_cnt, 0u);
            __threadfence();
            g_gen = gen + 1;
        } else {
            while (g_gen == gen) { __nanosleep(64); }
        }
        __threadfence();           // acquire (CCTL.IVALL -> fresh L1)
    }
    __syncthreads();
}

// ---------------- one-time: Xenc[t] = embed(x[:,t]) @ enc_wx + enc_b -------
__global__ __launch_bounds__(256) void k_enc_pre(
    const int* __restrict__ x, const float* __restrict__ emb,
    const float* __restrict__ wx, const float* __restrict__ bias)
{
    __shared__ __align__(16) float As[32][34];
    int tid = threadIdx.x;
    int t = blockIdx.z;
    int txq = tid & 31, ty = tid >> 5;
    int c0 = blockIdx.x * 128 + txq * 4;
    int lb = tid >> 3, lk = (tid & 7) * 4;
    int tok = x[lb * LL + t];
    const float* arow = emb + (size_t)tok * EE;

    ull acc[4][2];
#pragma unroll
    for (int j = 0; j < 4; j++) { acc[j][0] = 0; acc[j][1] = 0; }

    for (int kc = 0; kc < EE; kc += 32) {
        __syncthreads();
        float4 v = *(const float4*)(arow + kc + lk);
        As[lk + 0][lb] = v.x; As[lk + 1][lb] = v.y;
        As[lk + 2][lb] = v.z; As[lk + 3][lb] = v.w;
        __syncthreads();
#pragma unroll 8
        for (int kk = 0; kk < 32; kk++) {
            float4 w4 = *(const float4*)(wx + (size_t)(kc + kk) * G4 + c0);
            ull wp0 = pk2(w4.x), wp1 = pk2(w4.y), wp2 = pk2(w4.z), wp3 = pk2(w4.w);
            ull a0 = *(const ull*)&As[kk][ty * 4];
            ull a1 = *(const ull*)&As[kk][ty * 4 + 2];
            fma2(acc[0][0], a0, wp0); fma2(acc[0][1], a1, wp0);
            fma2(acc[1][0], a0, wp1); fma2(acc[1][1], a1, wp1);
            fma2(acc[2][0], a0, wp2); fma2(acc[2][1], a1, wp2);
            fma2(acc[3][0], a0, wp3); fma2(acc[3][1], a1, wp3);
        }
    }
    float4 bv = *(const float4*)(bias + c0);
    float bj[4] = {bv.x, bv.y, bv.z, bv.w};
    float* outt = g_Xenc + (size_t)t * BB * G4;
#pragma unroll
    for (int j = 0; j < 4; j++) {
        int c = c0 + j;
#pragma unroll
        for (int rp = 0; rp < 2; rp++) {
            float2 v = upk(acc[j][rp]);
            int row = ty * 4 + rp * 2;
            outt[row * G4 + c]       = v.x + bj[j];
            outt[(row + 1) * G4 + c] = v.y + bj[j];
        }
    }
}

// ============ 256-col x 32-row GEMM core, KSTEP=16, double buffered ========
// Warp geometry: 8 warps own 32-col ranges; within warp 4 col-lanes x 8
// row-lanes. Thread = 8 cols (4 f32x2 col-pairs) x 4 rows. 16 FMA2 per kk.
// Smem traffic/warp-kk: W 2x LDS.128 (64B distinct, 8-way bcast) +
// A 2x LDS.128 (256B distinct over 8 row-lanes, quad bcast).
// Ws: float[2][16][256] (32KB). Au: ull[2][16][34] (stride 272B = 17*16 ->
// every [kk][rl*4] ulonglong2 access stays 16B-aligned; [33] traps).
#define G256_LOOP(ACCBODY)                                                    \
    float (*Ws)[16][256] = (float(*)[16][256])SM;                             \
    ull   (*Au)[16][34]  = (ull(*)[16][34])(SM + 32768);                      \
    int tid = threadIdx.x;                                                    \
    int lane = tid & 31, wrp = tid >> 5;                                      \
    int cl = lane & 3, rl = lane >> 2;                                        \
    int wcol = wrp * 32 + cl * 8;                                             \
    int wk = tid >> 6, wf = tid & 63;                                         \
    int ab = tid >> 2, aq = (tid & 3) * 4;                                    \
    float4 wld[4]; float4 av = make_float4(0.f, 0.f, 0.f, 0.f);               \
    _Pragma("unroll")                                                         \
    for (int p = 0; p < 4; p++)                                               \
        wld[p] = LDW(Wb + (size_t)(wk + p * 4) * ldW + cb + wf * 4);          \
    if (tid < 128) av = *(const float4*)(Ab + ab * DH + aq);                  \
    ull acc[4][4];                                                            \
    _Pragma("unroll")                                                         \
    for (int cp = 0; cp < 4; cp++)                                            \
        _Pragma("unroll")                                                     \
        for (int r = 0; r < 4; r++) acc[cp][r] = 0;                           \
    int buf = 0;                                                              \
    for (int kc = 0; kc < KC; kc += 16) {                                     \
        _Pragma("unroll")                                                     \
        for (int p = 0; p < 4; p++)                                           \
            *(float4*)&Ws[buf][wk + p * 4][wf * 4] = wld[p];                  \
        if (tid < 128) {                                                      \
            Au[buf][aq + 0][ab] = pk2(av.x);                                  \
            Au[buf][aq + 1][ab] = pk2(av.y);                                  \
            Au[buf][aq + 2][ab] = pk2(av.z);                                  \
            Au[buf][aq + 3][ab] = pk2(av.w);                                  \
        }                                                                     \
        __syncthreads();                                                      \
        if (kc + 16 < KC) {                                                   \
            const float* wn = Wb + (size_t)(kc + 16) * ldW;                   \
            _Pragma("unroll")                                                 \
            for (int p = 0; p < 4; p++)                                       \
                wld[p] = LDW(wn + (size_t)(wk + p * 4) * ldW + cb + wf * 4);  \
            if (tid < 128)                                                    \
                av = *(const float4*)(Ab + ab * DH + kc + 16 + aq);           \
        }                                                                     \
        _Pragma("unroll")                                                     \
        for (int kk = 0; kk < 16; kk++) {                                     \
            ulonglong2 wA = *(const ulonglong2*)&Ws[buf][kk][wcol];           \
            ulonglong2 wB = *(const ulonglong2*)&Ws[buf][kk][wcol + 4];       \
            ulonglong2 aA = *(const ulonglong2*)&Au[buf][kk][rl * 4];         \
            ulonglong2 aB = *(const ulonglong2*)&Au[buf][kk][rl * 4 + 2];     \
            fma2(acc[0][0], wA.x, aA.x); fma2(acc[0][1], wA.x, aA.y);         \
            fma2(acc[0][2], wA.x, aB.x); fma2(acc[0][3], wA.x, aB.y);         \
            fma2(acc[1][0], wA.y, aA.x); fma2(acc[1][1], wA.y, aA.y);         \
            fma2(acc[1][2], wA.y, aB.x); fma2(acc[1][3], wA.y, aB.y);         \
            fma2(acc[2][0], wB.x, aA.x); fma2(acc[2][1], wB.x, aA.y);         \
            fma2(acc[2][2], wB.x, aB.x); fma2(acc[2][3], wB.x, aB.y);         \
            fma2(acc[3][0], wB.y, aA.x); fma2(acc[3][1], wB.y, aA.y);         \
            fma2(acc[3][2], wB.y, aB.x); fma2(acc[3][3], wB.y, aB.y);         \
        }                                                                     \
        buf ^= 1;                                                             \
    }                                                                         \
    __syncthreads();                                                          \
    ACCBODY
// acc[cp][r] = cols (cb+wcol+2cp, +1) x row (rl*4 + r)

// partial-writing variant (encoder / gates)
__device__ __forceinline__ void gemm256(
    const float* __restrict__ Ab, const float* __restrict__ Wb,
    int ldW, int KC, float* __restrict__ outp, int Nout, int cb, char* SM)
{
#define LDW(p) (*(const float4*)(p))
    G256_LOOP({
#pragma unroll
        for (int r = 0; r < 4; r++) {
            int row = rl * 4 + r;
#pragma unroll
            for (int cp = 0; cp < 4; cp++) {
                float2 v = upk(acc[cp][r]);
                *(float2*)&outp[(size_t)row * Nout + cb + wcol + 2 * cp] = v;
            }
        }
    })
#undef LDW
}

// outproj variant: streams out_w, adds bias, writes logits, fused per-tile
// max/argmax/expsum (shfl over 4 col-lanes, then cross-warp merge in smem).
__device__ __forceinline__ void outproj256(
    const float* __restrict__ Ab, const float* __restrict__ Wb,
    int ldW, int KC, const float* __restrict__ bias,
    float* __restrict__ out, int t, int tile, int cb, char* SM)
{
#define LDW(p) __ldcs((const float4*)(p))
    G256_LOOP({
        float* smax = (float*)SM;                 // [32][8]
        float* ssum = smax + 256;                 // [32][8]
        int*   sidx = (int*)(ssum + 256);         // [32][8]
        float2 bv[4];
#pragma unroll
        for (int cp = 0; cp < 4; cp++)
            bv[cp] = *(const float2*)&bias[cb + wcol + 2 * cp];
#pragma unroll
        for (int r = 0; r < 4; r++) {
            int row = rl * 4 + r;
            float v[8];
#pragma unroll
            for (int cp = 0; cp < 4; cp++) {
                float2 x = upk(acc[cp][r]);
                v[cp * 2]     = x.x + bv[cp].x;
                v[cp * 2 + 1] = x.y + bv[cp].y;
            }
            float* orow = out + ((size_t)(row * LL + t)) * VV + cb + wcol;
#pragma unroll
            for (int cp = 0; cp < 4; cp++)
                *(float2*)&orow[cp * 2] = make_float2(v[cp * 2], v[cp * 2 + 1]);
            // local max/argmax (ascending cols -> first-max-wins)
            float m = v[0]; int mi = cb + wcol;
#pragma unroll
            for (int cc = 1; cc < 8; cc++)
                if (v[cc] > m) { m = v[cc]; mi = cb + wcol + cc; }
            // reduce over the 4 col-lanes (xor 1,2 stay within the quad)
#pragma unroll
            for (int o = 1; o <= 2; o <<= 1) {
                float om = __shfl_xor_sync(0xFFFFFFFFu, m, o);
                int   oi = __shfl_xor_sync(0xFFFFFFFFu, mi, o);
                if (om > m || (om == m && oi < mi)) { m = om; mi = oi; }
            }
            float s = 0.f;
#pragma unroll
            for (int cc = 0; cc < 8; cc++) s += __expf(v[cc] - m);
#pragma unroll
            for (int o = 1; o <= 2; o <<= 1)
                s += __shfl_xor_sync(0xFFFFFFFFu, s, o);
            if (cl == 0) {
                smax[row * 8 + wrp] = m;
                ssum[row * 8 + wrp] = s;
                sidx[row * 8 + wrp] = mi;
            }
        }
        __syncthreads();
        if (tid < 32) {
            int row = tid;
            float M = smax[row * 8]; int I = sidx[row * 8];
#pragma unroll
            for (int w2 = 1; w2 < 8; w2++) {
                float om = smax[row * 8 + w2];
                if (om > M) { M = om; I = sidx[row * 8 + w2]; }  // asc cols
            }
            float S = 0.f;
#pragma unroll
            for (int w2 = 0; w2 < 8; w2++)
                S += ssum[row * 8 + w2] * __expf(smax[row * 8 + w2] - M);
            g_pm[row][tile] = M;
            g_ps[row][tile] = S;
            g_pi[row][tile] = I;
        }
        __syncthreads();
    })
#undef LDW
}

// ---------------- 64-col GEMM core (comb only), KSTEP=32 -------------------
__device__ __forceinline__ void gemm64(
    const float* __restrict__ Ab, const float* __restrict__ Wb,
    int ldW, int KC, float* __restrict__ outp, int Nout, int cb, char* SM)
{
    float (*Ws)[32][64] = (float(*)[32][64])SM;
    ull   (*Au)[32][34] = (ull(*)[32][34])(SM + 16384);
    int tid = threadIdx.x;
    int cg = tid & 15, tr = tid >> 4;
    int wr0 = tid >> 4, wc0 = (tid & 15) * 4;
    int lb = tid >> 3, lk = (tid & 7) * 4;

    float4 w0 = *(const float4*)(Wb + (size_t)wr0 * ldW + cb + wc0);
    float4 w1 = *(const float4*)(Wb + (size_t)(wr0 + 16) * ldW + cb + wc0);
    float4 av = *(const float4*)(Ab + lb * DH + lk);

    ull acc[2][2] = {{0, 0}, {0, 0}};
    int buf = 0;
    for (int kc = 0; kc < KC; kc += 32) {
        *(float4*)&Ws[buf][wr0][wc0]      = w0;
        *(float4*)&Ws[buf][wr0 + 16][wc0] = w1;
        Au[buf][lk + 0][lb] = pk2(av.x);
        Au[buf][lk + 1][lb] = pk2(av.y);
        Au[buf][lk + 2][lb] = pk2(av.z);
        Au[buf][lk + 3][lb] = pk2(av.w);
        __syncthreads();
        if (kc + 32 < KC) {
            const float* wp = Wb + (size_t)(kc + 32) * ldW;
            w0 = *(const float4*)(wp + (size_t)wr0 * ldW + cb + wc0);
            w1 = *(const float4*)(wp + (size_t)(wr0 + 16) * ldW + cb + wc0);
            av = *(const float4*)(Ab + lb * DH + kc + 32 + lk);
        }
#pragma unroll
        for (int kk = 0; kk < 32; kk++) {
            ulonglong2 wv = *(const ulonglong2*)&Ws[buf][kk][cg * 4];
            ulonglong2 a2 = *(const ulonglong2*)&Au[buf][kk][tr * 2];
            fma2(acc[0][0], wv.x, a2.x); fma2(acc[0][1], wv.y, a2.x);
            fma2(acc[1][0], wv.x, a2.y); fma2(acc[1][1], wv.y, a2.y);
        }
        buf ^= 1;
    }
    __syncthreads();
    int r0 = tr * 2;
#pragma unroll
    for (int cp = 0; cp < 2; cp++) {
        int c = cb + cg * 4 + 2 * cp;
        float2 v0 = upk(acc[0][cp]);
        float2 v1 = upk(acc[1][cp]);
        *(float2*)&outp[(size_t)r0 * Nout + c]       = v0;
        *(float2*)&outp[(size_t)(r0 + 1) * Nout + c] = v1;
    }
}

// ---------------- LSTM reduce unit (8 split-K partials) --------------------
__device__ __forceinline__ void lstm_reduce_unit(
    int gid, const float* bias, int use_xadd, int t, int store_enc)
{
    int base = gid * 4;
    int b = base >> 10, d = base & 1023;
    const float4* xadd = (const float4*)(g_Xenc + (size_t)t * BB * G4);
    float4 gv[4];
#pragma unroll
    for (int g = 0; g < 4; g++) {
        int off4 = (b * G4 + g * DH + d) >> 2;
        float4 s = bias ? ((const float4*)bias)[(g * DH + d) >> 2]
                        : make_float4(0.f, 0.f, 0.f, 0.f);
        if (use_xadd) {
            float4 xv = xadd[off4];
            s.x += xv.x; s.y += xv.y; s.z += xv.z; s.w += xv.w;
        }
#pragma unroll
        for (int sp = 0; sp < 8; sp++) {
            float4 p = ((const float4*)g_part)[sp * (BB * G4 / 4) + off4];
            s.x += p.x; s.y += p.y; s.z += p.z; s.w += p.w;
        }
        gv[g] = s;
    }
    float4 cold = ((const float4*)g_c)[gid];
    float4 cn, hn;
    {
        float* iv = (float*)&gv[0]; float* fv = (float*)&gv[1];
        float* gg = (float*)&gv[2]; float* ov = (float*)&gv[3];
        float* cp = (float*)&cold; float* cnp = (float*)&cn; float* hnp = (float*)&hn;
#pragma unroll
        for (int j = 0; j < 4; j++) {
            float cc = sigm(fv[j]) * cp[j] + sigm(iv[j]) * tanhf(gg[j]);
            cnp[j] = cc;
            hnp[j] = sigm(ov[j]) * tanhf(cc);
        }
    }
    ((float4*)g_c)[gid] = cn;
    ((float4*)g_h)[gid] = hn;
    if (store_enc)
        ((float4*)g_enc_outs)[((b * LL + t) * DH + d) >> 2] = hn;
}

// ---------------- THE persistent kernel ------------------------------------
__global__ __launch_bounds__(256, 1) void k_persist(
    const float* __restrict__ enc_wh,
    const float* __restrict__ dec_embed, const float* __restrict__ attn_w,
    const float* __restrict__ attn_b,
    const float* __restrict__ comb_w, const float* __restrict__ comb_b,
    const float* __restrict__ dec_wx, const float* __restrict__ dec_wh,
    const float* __restrict__ dec_b,
    const float* __restrict__ out_w, const float* __restrict__ out_b,
    float* __restrict__ out)
{
    __shared__ __align__(16) char SM[41984];
    int bx = blockIdx.x, tid = threadIdx.x;
    int nb = gridDim.x;
    int nthr = nb * 256;
    int gid0 = bx * 256 + tid;

    // ---- init h=c=0 ----
    for (int u = gid0; u < BB * DH / 4; u += nthr) {
        ((float4*)g_h)[u] = make_float4(0.f, 0.f, 0.f, 0.f);
        ((float4*)g_c)[u] = make_float4(0.f, 0.f, 0.f, 0.f);
    }
    gsync();

    // ================= encoder: 64 steps =================
    for (int t = 0; t < LL; t++) {
        for (int u = bx; u < 128; u += nb) {      // 16 tiles x 8 splits (KC=128)
            int ct = u & 15, sp = u >> 4;
            int k0 = sp * 128;
            gemm256(g_h + k0, enc_wh + (size_t)k0 * G4, G4, 128,
                    g_part + (size_t)sp * BB * G4, G4, ct * 256, SM);
            __syncthreads();
        }
        gsync();
        for (int u = gid0; u < BB * DH / 4; u += nthr)
            lstm_reduce_unit(u, nullptr, 1, t, 1);
        gsync();
    }

    // ---- decoder init ----
    for (int u = gid0; u < BB * DH / 4; u += nthr) {
        ((float4*)g_h)[u] = make_float4(0.f, 0.f, 0.f, 0.f);
        ((float4*)g_c)[u] = make_float4(0.f, 0.f, 0.f, 0.f);
    }
    if (gid0 < BB) g_tok[gid0] = 127;
    gsync();

    // ================= decoder: 64 steps =================
    for (int t = 0; t < LL; t++) {
        // ---- P1: attention (32 units, one per batch row) ----
        for (int b = bx; b < BB; b += nb) {
            float* se  = (float*)SM;
            float* sh  = se + DH;
            float* sc  = sh + DH;
            float* sp4 = sc + 64;
            float* red = sp4 + 256;
            int tok = g_tok[b];
            for (int k = tid; k < DH; k += 256) {
                float e = dec_embed[(size_t)tok * DH + k];
                se[k] = e;
                g_e[b * DH + k] = e;
                sh[k] = g_h[b * DH + k];
            }
            __syncthreads();
            int l = tid & 63, kg = tid >> 6;
            const float* src = (kg < 2) ? (se + kg * 512) : (sh + (kg - 2) * 512);
            const float* wbase = attn_w + (size_t)(kg * 512) * LL + l;
            float p0 = 0.f, p1 = 0.f, p2 = 0.f, p3 = 0.f;
            float p4 = 0.f, p5 = 0.f, p6 = 0.f, p7 = 0.f;
#pragma unroll 2
            for (int kk = 0; kk < 512; kk += 8) {
                p0 += src[kk + 0] * wbase[(size_t)(kk + 0) * LL];
                p1 += src[kk + 1] * wbase[(size_t)(kk + 1) * LL];
                p2 += src[kk + 2] * wbase[(size_t)(kk + 2) * LL];
                p3 += src[kk + 3] * wbase[(size_t)(kk + 3) * LL];
                p4 += src[kk + 4] * wbase[(size_t)(kk + 4) * LL];
                p5 += src[kk + 5] * wbase[(size_t)(kk + 5) * LL];
                p6 += src[kk + 6] * wbase[(size_t)(kk + 6) * LL];
                p7 += src[kk + 7] * wbase[(size_t)(kk + 7) * LL];
            }
            sp4[kg * 64 + l] = ((p0 + p1) + (p2 + p3)) + ((p4 + p5) + (p6 + p7));
            __syncthreads();
            if (tid < 64)
                sc[tid] = sp4[tid] + sp4[64 + tid] + sp4[128 + tid] + sp4[192 + tid]
                        + attn_b[tid];
            __syncthreads();
            if (tid < 64) red[tid] = sc[tid];
            __syncthreads();
            for (int off = 32; off >= 1; off >>= 1) {
                if (tid < off) red[tid] = fmaxf(red[tid], red[tid + off]);
                __syncthreads();
            }
            float mx = red[0];
            __syncthreads();
            if (tid < 64) { float e = expf(sc[tid] - mx); sc[tid] = e; red[tid] = e; }
            __syncthreads();
            for (int off = 32; off >= 1; off >>= 1) {
                if (tid < off) red[tid] += red[tid + off];
                __syncthreads();
            }
            float inv = 1.f / red[0];
            __syncthreads();
            if (tid < 64) sc[tid] *= inv;
            __syncthreads();
            float4 acc4 = make_float4(0.f, 0.f, 0.f, 0.f);
            const float4* eob = (const float4*)(g_enc_outs + (size_t)b * LL * DH);
#pragma unroll 4
            for (int l2 = 0; l2 < LL; l2++) {
                float a = sc[l2];
                float4 e4 = eob[l2 * 256 + tid];
                acc4.x += a * e4.x; acc4.y += a * e4.y;
                acc4.z += a * e4.z; acc4.w += a * e4.w;
            }
            ((float4*)(g_ctx + b * DH))[tid] = acc4;
            __syncthreads();
        }
        gsync();

        // ---- P2: comb gemm (16 tiles x 8 splits, KC=256) ----
        for (int u = bx; u < 128; u += nb) {
            int ct = u & 15, sp = u >> 4;
            int k0 = sp * 256;
            const float* Ab = (k0 < DH) ? (g_e + k0) : (g_ctx + k0 - DH);
            gemm64(Ab, comb_w + (size_t)k0 * DH, DH, 256,
                   g_part + (size_t)sp * BB * DH, DH, ct * 64, SM);
            __syncthreads();
        }
        gsync();

        // ---- P3: comb reduce + relu ----
        for (int u = gid0; u < BB * DH / 4; u += nthr) {
            int d = (u * 4) & 1023;
            float4 s = ((const float4*)comb_b)[d >> 2];
#pragma unroll
            for (int sp = 0; sp < 8; sp++) {
                float4 p = ((const float4*)g_part)[sp * (BB * DH / 4) + u];
                s.x += p.x; s.y += p.y; s.z += p.z; s.w += p.w;
            }
            s.x = fmaxf(s.x, 0.f); s.y = fmaxf(s.y, 0.f);
            s.z = fmaxf(s.z, 0.f); s.w = fmaxf(s.w, 0.f);
            ((float4*)g_inp)[u] = s;
        }
        gsync();

        // ---- P4: gates gemm (16 tiles x 8 splits over K=2048, KC=256) ----
        for (int u = bx; u < 128; u += nb) {
            int ct = u & 15, sp = u >> 4;
            int k0 = sp * 256;
            const float* Ab = (k0 < DH) ? (g_inp + k0) : (g_h + k0 - DH);
            const float* Wb = (k0 < DH) ? (dec_wx + (size_t)k0 * G4)
                                        : (dec_wh + (size_t)(k0 - DH) * G4);
            gemm256(Ab, Wb, G4, 256,
                    g_part + (size_t)sp * BB * G4, G4, ct * 256, SM);
            __syncthreads();
        }
        gsync();

        // ---- P5: LSTM reduce ----
        for (int u = gid0; u < BB * DH / 4; u += nthr)
            lstm_reduce_unit(u, dec_b, 0, t, 0);
        gsync();

        // ---- P6: output projection + fused per-tile softmax stats ----
        for (int u = bx; u < NTILES_OP; u += nb) {
            outproj256(g_h, out_w, VV, DH, out_b, out, t, u, u * 256, SM);
            __syncthreads();
        }
        gsync();

        // ---- P7: merge tile stats, subtract lse, emit token ----
        for (int u = bx; u < 256; u += nb) {
            int j = u & 7, b = u >> 3;
            float M = -1e30f;
            for (int jj = 0; jj < NTILES_OP; jj++) M = fmaxf(M, g_pm[b][jj]);
            float S = 0.f;
            for (int jj = 0; jj < NTILES_OP; jj++)
                S += g_ps[b][jj] * __expf(g_pm[b][jj] - M);
            float lse = M + logf(S);
            float4* row4 = (float4*)(out + ((size_t)(b * LL + t)) * VV) + j * 1000;
            for (int i = tid; i < 1000; i += 256) {
                float4 v = row4[i];
                v.x -= lse; v.y -= lse; v.z -= lse; v.w -= lse;
                row4[i] = v;
            }
            if (j == 0 && tid == 0) {
                float bm = -1e30f; int bi = 0;
                for (int jj = 0; jj < NTILES_OP; jj++) {
                    if (g_pm[b][jj] > bm) { bm = g_pm[b][jj]; bi = g_pi[b][jj]; }
                }
                g_tok[b] = bi;   // tiles ascend in col; strict > keeps first max
            }
        }
        gsync();
    }
}

// ---------------- host launcher --------------------------------------------
extern "C" void kernel_launch(void* const* d_in, const int* in_sizes, int n_in,
                              void* d_out, int out_size)
{
    (void)in_sizes; (void)n_in; (void)out_size;
    const int*   x         = (const int*)  d_in[0];
    const float* enc_embed = (const float*)d_in[1];
    const float* enc_wx    = (const float*)d_in[2];
    const float* enc_wh    = (const float*)d_in[3];
    const float* enc_b     = (const float*)d_in[4];
    const float* dec_embed = (const float*)d_in[5];
    const float* attn_w    = (const float*)d_in[6];
    const float* attn_b    = (const float*)d_in[7];
    const float* comb_w    = (const float*)d_in[8];
    const float* comb_b    = (const float*)d_in[9];
    const float* dec_wx    = (const float*)d_in[10];
    const float* dec_wh    = (const float*)d_in[11];
    const float* dec_b     = (const float*)d_in[12];
    const float* out_w     = (const float*)d_in[13];
    const float* out_b     = (const float*)d_in[14];
    float* out = (float*)d_out;

    int dev = 0, nsm = MAXBLK;
    cudaGetDevice(&dev);
    cudaDeviceGetAttribute(&nsm, cudaDevAttrMultiProcessorCount, dev);
    int nblk = nsm < MAXBLK ? nsm : MAXBLK;

    k_enc_pre<<<dim3(32, 1, 64), 256>>>(x, enc_embed, enc_wx, enc_b);
    k_persist<<<nblk, 256>>>(enc_wh, dec_embed, attn_w, attn_b,
                             comb_w, comb_b, dec_wx, dec_wh, dec_b,
                             out_w, out_b, out);
}

// round 15
// speedup vs baseline: 3.1197x; 1.0541x over previous
#include <cuda_runtime.h>
#include <math.h>

// Problem constants
#define BB 32
#define LL 64
#define EE 512
#define DH 1024
#define G4 4096
#define VV 32000
#define MAXBLK 148
#define NTILES_OP 125   // 32000 / 256

typedef unsigned long long ull;

// ---------------- scratch (device globals; no allocation allowed) ----------
__device__ __align__(16) float g_Xenc[LL * BB * G4];      // embed@enc_wx + enc_b
__device__ __align__(16) float g_enc_outs[BB * LL * DH];  // encoder hidden states
__device__ __align__(16) float g_part[8 * BB * G4];       // gates/enc split-K partials
__device__ __align__(16) float g_part2[8 * BB * DH];      // comb split-K partials
__device__ __align__(16) float g_h[BB * DH];
__device__ __align__(16) float g_c[BB * DH];
__device__ __align__(16) float g_e[BB * DH];
__device__ __align__(16) float g_ctx[BB * DH];
__device__ float g_pm[BB][128];   // per-outproj-tile max
__device__ float g_ps[BB][128];   // per-outproj-tile sum exp(x - tilemax)
__device__ int   g_pi[BB][128];   // per-outproj-tile argmax
__device__ float g_lse[BB][LL];   // log-sum-exp per (b, t), subtracted in epilogue

// grid barrier state (flag per block + generation; monotonic across replays)
__device__ volatile unsigned g_flags[MAXBLK];
__device__ volatile unsigned g_gen2;

// ---------------- f32x2 helpers (sm_103a packed FMA) -----------------------
__device__ __forceinline__ ull pk2(float w) {
    ull r; asm("mov.b64 %0, {%1, %1};" : "=l"(r) : "f"(w)); return r;
}
__device__ __forceinline__ void fma2(ull& d, ull a, ull b) {
    asm("fma.rn.f32x2 %0, %1, %2, %0;" : "+l"(d) : "l"(a), "l"(b));
}
__device__ __forceinline__ float2 upk(ull v) {
    float2 f; asm("mov.b64 {%0, %1}, %2;" : "=f"(f.x), "=f"(f.y) : "l"(v)); return f;
}
__device__ __forceinline__ float sigm(float x) { return 1.0f / (1.0f + expf(-x)); }

// ---------------- device-wide barrier: flag array + leader -----------------
// Arrival = one plain volatile store (no atomic serialization). Block 0's
// first gridDim.x threads each watch one flag in parallel, then publish.
// Generation counters are monotonic (wrap-safe via signed diff) so state is
// consistent across graph replays.
__device__ __forceinline__ void gsync() {
    __threadfence();               // release: my writes visible at L2
    __syncthreads();
    int tid = threadIdx.x, bx = blockIdx.x, nb = gridDim.x;
    if (bx == 0) {
        unsigned target = g_gen2 + 1;
        if (tid == 0) g_flags[0] = target;
        if (tid > 0 && tid < nb)
            while ((int)(g_flags[tid] - target) < 0) __nanosleep(32);
        __syncthreads();
        if (tid == 0) { __threadfence(); g_gen2 = target; }
    } else {
        if (tid == 0) {
            unsigned target = g_gen2 + 1;
            g_flags[bx] = target;
            while ((int)(g_gen2 - target) < 0) __nanosleep(32);
            __threadfence();       // acquire: L1 invalidate before reads
        }
    }
    __syncthreads();
}

// ---------------- one-time: Xenc[t] = embed(x[:,t]) @ enc_wx + enc_b -------
__global__ __launch_bounds__(256) void k_enc_pre(
    const int* __restrict__ x, const float* __restrict__ emb,
    const float* __restrict__ wx, const float* __restrict__ bias)
{
    __shared__ __align__(16) float As[32][34];
    int tid = threadIdx.x;
    int t = blockIdx.z;
    int txq = tid & 31, ty = tid >> 5;
    int c0 = blockIdx.x * 128 + txq * 4;
    int lb = tid >> 3, lk = (tid & 7) * 4;
    int tok = x[lb * LL + t];
    const float* arow = emb + (size_t)tok * EE;

    ull acc[4][2];
#pragma unroll
    for (int j = 0; j < 4; j++) { acc[j][0] = 0; acc[j][1] = 0; }

    for (int kc = 0; kc < EE; kc += 32) {
        __syncthreads();
        float4 v = *(const float4*)(arow + kc + lk);
        As[lk + 0][lb] = v.x; As[lk + 1][lb] = v.y;
        As[lk + 2][lb] = v.z; As[lk + 3][lb] = v.w;
        __syncthreads();
#pragma unroll 8
        for (int kk = 0; kk < 32; kk++) {
            float4 w4 = *(const float4*)(wx + (size_t)(kc + kk) * G4 + c0);
            ull wp0 = pk2(w4.x), wp1 = pk2(w4.y), wp2 = pk2(w4.z), wp3 = pk2(w4.w);
            ull a0 = *(const ull*)&As[kk][ty * 4];
            ull a1 = *(const ull*)&As[kk][ty * 4 + 2];
            fma2(acc[0][0], a0, wp0); fma2(acc[0][1], a1, wp0);
            fma2(acc[1][0], a0, wp1); fma2(acc[1][1], a1, wp1);
            fma2(acc[2][0], a0, wp2); fma2(acc[2][1], a1, wp2);
            fma2(acc[3][0], a0, wp3); fma2(acc[3][1], a1, wp3);
        }
    }
    float4 bv = *(const float4*)(bias + c0);
    float bj[4] = {bv.x, bv.y, bv.z, bv.w};
    float* outt = g_Xenc + (size_t)t * BB * G4;
#pragma unroll
    for (int j = 0; j < 4; j++) {
        int c = c0 + j;
#pragma unroll
        for (int rp = 0; rp < 2; rp++) {
            float2 v = upk(acc[j][rp]);
            int row = ty * 4 + rp * 2;
            outt[row * G4 + c]       = v.x + bj[j];
            outt[(row + 1) * G4 + c] = v.y + bj[j];
        }
    }
}

// fused A-loader for the gates GEMM: reduce 8 comb partials + bias + relu
__device__ __forceinline__ float4 comb_fetch(
    const float* __restrict__ combb, int row, int d)
{
    float4 s = *(const float4*)(combb + d);
    const float* base = g_part2 + (size_t)row * DH + d;
#pragma unroll
    for (int sp = 0; sp < 8; sp++) {
        float4 p = *(const float4*)(base + (size_t)sp * (BB * DH));
        s.x += p.x; s.y += p.y; s.z += p.z; s.w += p.w;
    }
    s.x = fmaxf(s.x, 0.f); s.y = fmaxf(s.y, 0.f);
    s.z = fmaxf(s.z, 0.f); s.w = fmaxf(s.w, 0.f);
    return s;
}

// ============ 256-col x 32-row GEMM core, KSTEP=16, double buffered ========
// Warp geometry: 8 warps own 32-col ranges; within warp 4 col-lanes x 8
// row-lanes. Thread = 8 cols (4 f32x2 col-pairs) x 4 rows. 16 FMA2 per kk.
// Ws: float[2][16][256] (32KB). Au: ull[2][16][34] (stride 272B = 17*16 ->
// every [kk][rl*4] ulonglong2 access stays 16B-aligned).
// LDW(ptr) loads a W float4; LDA(off) produces this thread's A float4.
#define G256_LOOP(ACCBODY)                                                    \
    float (*Ws)[16][256] = (float(*)[16][256])SM;                             \
    ull   (*Au)[16][34]  = (ull(*)[16][34])(SM + 32768);                      \
    int tid = threadIdx.x;                                                    \
    int lane = tid & 31, wrp = tid >> 5;                                      \
    int cl = lane & 3, rl = lane >> 2;                                        \
    int wcol = wrp * 32 + cl * 8;                                             \
    int wk = tid >> 6, wf = tid & 63;                                         \
    int ab = tid >> 2, aq = (tid & 3) * 4;                                    \
    (void)ab; (void)aq;                                                       \
    float4 wld[4]; float4 av = make_float4(0.f, 0.f, 0.f, 0.f);               \
    _Pragma("unroll")                                                         \
    for (int p = 0; p < 4; p++)                                               \
        wld[p] = LDW(Wb + (size_t)(wk + p * 4) * ldW + cb + wf * 4);          \
    if (tid < 128) av = LDA(0);                                               \
    ull acc[4][4];                                                            \
    _Pragma("unroll")                                                         \
    for (int cp = 0; cp < 4; cp++)                                            \
        _Pragma("unroll")                                                     \
        for (int r = 0; r < 4; r++) acc[cp][r] = 0;                           \
    int buf = 0;                                                              \
    for (int kc = 0; kc < KC; kc += 16) {                                     \
        _Pragma("unroll")                                                     \
        for (int p = 0; p < 4; p++)                                           \
            *(float4*)&Ws[buf][wk + p * 4][wf * 4] = wld[p];                  \
        if (tid < 128) {                                                      \
            Au[buf][aq + 0][ab] = pk2(av.x);                                  \
            Au[buf][aq + 1][ab] = pk2(av.y);                                  \
            Au[buf][aq + 2][ab] = pk2(av.z);                                  \
            Au[buf][aq + 3][ab] = pk2(av.w);                                  \
        }                                                                     \
        __syncthreads();                                                      \
        if (kc + 16 < KC) {                                                   \
            const float* wn = Wb + (size_t)(kc + 16) * ldW;                   \
            _Pragma("unroll")                                                 \
            for (int p = 0; p < 4; p++)                                       \
                wld[p] = LDW(wn + (size_t)(wk + p * 4) * ldW + cb + wf * 4);  \
            if (tid < 128) av = LDA(kc + 16);                                 \
        }                                                                     \
        _Pragma("unroll")                                                     \
        for (int kk = 0; kk < 16; kk++) {                                     \
            ulonglong2 wA = *(const ulonglong2*)&Ws[buf][kk][wcol];           \
            ulonglong2 wB = *(const ulonglong2*)&Ws[buf][kk][wcol + 4];       \
            ulonglong2 aA = *(const ulonglong2*)&Au[buf][kk][rl * 4];         \
            ulonglong2 aB = *(const ulonglong2*)&Au[buf][kk][rl * 4 + 2];     \
            fma2(acc[0][0], wA.x, aA.x); fma2(acc[0][1], wA.x, aA.y);         \
            fma2(acc[0][2], wA.x, aB.x); fma2(acc[0][3], wA.x, aB.y);         \
            fma2(acc[1][0], wA.y, aA.x); fma2(acc[1][1], wA.y, aA.y);         \
            fma2(acc[1][2], wA.y, aB.x); fma2(acc[1][3], wA.y, aB.y);         \
            fma2(acc[2][0], wB.x, aA.x); fma2(acc[2][1], wB.x, aA.y);         \
            fma2(acc[2][2], wB.x, aB.x); fma2(acc[2][3], wB.x, aB.y);         \
            fma2(acc[3][0], wB.y, aA.x); fma2(acc[3][1], wB.y, aA.y);         \
            fma2(acc[3][2], wB.y, aB.x); fma2(acc[3][3], wB.y, aB.y);         \
        }                                                                     \
        buf ^= 1;                                                             \
    }                                                                         \
    __syncthreads();                                                          \
    ACCBODY
// acc[cp][r] = cols (cb+wcol+2cp, +1) x row (rl*4 + r)

#define WRITE_PARTIALS                                                        \
    {                                                                         \
        _Pragma("unroll")                                                     \
        for (int r = 0; r < 4; r++) {                                         \
            int row = rl * 4 + r;                                             \
            _Pragma("unroll")                                                 \
            for (int cp = 0; cp < 4; cp++) {                                  \
                float2 v = upk(acc[cp][r]);                                   \
                *(float2*)&outp[(size_t)row * Nout + cb + wcol + 2 * cp] = v; \
            }                                                                 \
        }                                                                     \
    }

// plain A (row-major, stride DH): encoder / gates-h / outproj
__device__ __forceinline__ void gemm256(
    const float* __restrict__ Ab, const float* __restrict__ Wb,
    int ldW, int KC, float* __restrict__ outp, int Nout, int cb, char* SM)
{
#define LDW(p) (*(const float4*)(p))
#define LDA(off) (*(const float4*)(Ab + ab * DH + (off) + aq))
    G256_LOOP(WRITE_PARTIALS)
#undef LDA
#undef LDW
}

// A = relu(comb partial-sum + comb_b) computed inline (gates gemm, k0 < DH)
__device__ __forceinline__ void gemm256_comb(
    int d0, const float* __restrict__ combb, const float* __restrict__ Wb,
    int ldW, int KC, float* __restrict__ outp, int Nout, int cb, char* SM)
{
#define LDW(p) (*(const float4*)(p))
#define LDA(off) comb_fetch(combb, ab, d0 + (off) + aq)
    G256_LOOP(WRITE_PARTIALS)
#undef LDA
#undef LDW
}

// outproj variant: streams out_w, adds bias, writes raw logits + per-tile
// max/argmax/expsum stats (lse subtraction deferred to the epilogue).
__device__ __forceinline__ void outproj256(
    const float* __restrict__ Ab, const float* __restrict__ Wb,
    int ldW, int KC, const float* __restrict__ bias,
    float* __restrict__ out, int t, int tile, int cb, char* SM)
{
#define LDW(p) __ldcs((const float4*)(p))
#define LDA(off) (*(const float4*)(Ab + ab * DH + (off) + aq))
    G256_LOOP({
        float* smax = (float*)SM;                 // [32][8]
        float* ssum = smax + 256;                 // [32][8]
        int*   sidx = (int*)(ssum + 256);         // [32][8]
        float2 bv[4];
#pragma unroll
        for (int cp = 0; cp < 4; cp++)
            bv[cp] = *(const float2*)&bias[cb + wcol + 2 * cp];
#pragma unroll
        for (int r = 0; r < 4; r++) {
            int row = rl * 4 + r;
            float v[8];
#pragma unroll
            for (int cp = 0; cp < 4; cp++) {
                float2 x = upk(acc[cp][r]);
                v[cp * 2]     = x.x + bv[cp].x;
                v[cp * 2 + 1] = x.y + bv[cp].y;
            }
            float* orow = out + ((size_t)(row * LL + t)) * VV + cb + wcol;
#pragma unroll
            for (int cp = 0; cp < 4; cp++)
                *(float2*)&orow[cp * 2] = make_float2(v[cp * 2], v[cp * 2 + 1]);
            float m = v[0]; int mi = cb + wcol;
#pragma unroll
            for (int cc = 1; cc < 8; cc++)
                if (v[cc] > m) { m = v[cc]; mi = cb + wcol + cc; }
#pragma unroll
            for (int o = 1; o <= 2; o <<= 1) {
                float om = __shfl_xor_sync(0xFFFFFFFFu, m, o);
                int   oi = __shfl_xor_sync(0xFFFFFFFFu, mi, o);
                if (om > m || (om == m && oi < mi)) { m = om; mi = oi; }
            }
            float s = 0.f;
#pragma unroll
            for (int cc = 0; cc < 8; cc++) s += __expf(v[cc] - m);
#pragma unroll
            for (int o = 1; o <= 2; o <<= 1)
                s += __shfl_xor_sync(0xFFFFFFFFu, s, o);
            if (cl == 0) {
                smax[row * 8 + wrp] = m;
                ssum[row * 8 + wrp] = s;
                sidx[row * 8 + wrp] = mi;
            }
        }
        __syncthreads();
        if (tid < 32) {
            int row = tid;
            float M = smax[row * 8]; int I = sidx[row * 8];
#pragma unroll
            for (int w2 = 1; w2 < 8; w2++) {
                float om = smax[row * 8 + w2];
                if (om > M) { M = om; I = sidx[row * 8 + w2]; }  // asc cols
            }
            float S = 0.f;
#pragma unroll
            for (int w2 = 0; w2 < 8; w2++)
                S += ssum[row * 8 + w2] * __expf(smax[row * 8 + w2] - M);
            g_pm[row][tile] = M;
            g_ps[row][tile] = S;
            g_pi[row][tile] = I;
        }
        __syncthreads();
    })
#undef LDA
#undef LDW
}

// ---------------- 64-col GEMM core (comb only), KSTEP=32 -------------------
__device__ __forceinline__ void gemm64(
    const float* __restrict__ Ab, const float* __restrict__ Wb,
    int ldW, int KC, float* __restrict__ outp, int Nout, int cb, char* SM)
{
    float (*Ws)[32][64] = (float(*)[32][64])SM;
    ull   (*Au)[32][34] = (ull(*)[32][34])(SM + 16384);
    int tid = threadIdx.x;
    int cg = tid & 15, tr = tid >> 4;
    int wr0 = tid >> 4, wc0 = (tid & 15) * 4;
    int lb = tid >> 3, lk = (tid & 7) * 4;

    float4 w0 = *(const float4*)(Wb + (size_t)wr0 * ldW + cb + wc0);
    float4 w1 = *(const float4*)(Wb + (size_t)(wr0 + 16) * ldW + cb + wc0);
    float4 av = *(const float4*)(Ab + lb * DH + lk);

    ull acc[2][2] = {{0, 0}, {0, 0}};
    int buf = 0;
    for (int kc = 0; kc < KC; kc += 32) {
        *(float4*)&Ws[buf][wr0][wc0]      = w0;
        *(float4*)&Ws[buf][wr0 + 16][wc0] = w1;
        Au[buf][lk + 0][lb] = pk2(av.x);
        Au[buf][lk + 1][lb] = pk2(av.y);
        Au[buf][lk + 2][lb] = pk2(av.z);
        Au[buf][lk + 3][lb] = pk2(av.w);
        __syncthreads();
        if (kc + 32 < KC) {
            const float* wp = Wb + (size_t)(kc + 32) * ldW;
            w0 = *(const float4*)(wp + (size_t)wr0 * ldW + cb + wc0);
            w1 = *(const float4*)(wp + (size_t)(wr0 + 16) * ldW + cb + wc0);
            av = *(const float4*)(Ab + lb * DH + kc + 32 + lk);
        }
#pragma unroll
        for (int kk = 0; kk < 32; kk++) {
            ulonglong2 wv = *(const ulonglong2*)&Ws[buf][kk][cg * 4];
            ulonglong2 a2 = *(const ulonglong2*)&Au[buf][kk][tr * 2];
            fma2(acc[0][0], wv.x, a2.x); fma2(acc[0][1], wv.y, a2.x);
            fma2(acc[1][0], wv.x, a2.y); fma2(acc[1][1], wv.y, a2.y);
        }
        buf ^= 1;
    }
    __syncthreads();
    int r0 = tr * 2;
#pragma unroll
    for (int cp = 0; cp < 2; cp++) {
        int c = cb + cg * 4 + 2 * cp;
        float2 v0 = upk(acc[0][cp]);
        float2 v1 = upk(acc[1][cp]);
        *(float2*)&outp[(size_t)r0 * Nout + c]       = v0;
        *(float2*)&outp[(size_t)(r0 + 1) * Nout + c] = v1;
    }
}

// ---------------- LSTM reduce unit (8 split-K partials) --------------------
__device__ __forceinline__ void lstm_reduce_unit(
    int gid, const float* bias, int use_xadd, int t, int store_enc)
{
    int base = gid * 4;
    int b = base >> 10, d = base & 1023;
    const float4* xadd = (const float4*)(g_Xenc + (size_t)t * BB * G4);
    float4 gv[4];
#pragma unroll
    for (int g = 0; g < 4; g++) {
        int off4 = (b * G4 + g * DH + d) >> 2;
        float4 s = bias ? ((const float4*)bias)[(g * DH + d) >> 2]
                        : make_float4(0.f, 0.f, 0.f, 0.f);
        if (use_xadd) {
            float4 xv = xadd[off4];
            s.x += xv.x; s.y += xv.y; s.z += xv.z; s.w += xv.w;
        }
#pragma unroll
        for (int sp = 0; sp < 8; sp++) {
            float4 p = ((const float4*)g_part)[sp * (BB * G4 / 4) + off4];
            s.x += p.x; s.y += p.y; s.z += p.z; s.w += p.w;
        }
        gv[g] = s;
    }
    float4 cold = ((const float4*)g_c)[gid];
    float4 cn, hn;
    {
        float* iv = (float*)&gv[0]; float* fv = (float*)&gv[1];
        float* gg = (float*)&gv[2]; float* ov = (float*)&gv[3];
        float* cp = (float*)&cold; float* cnp = (float*)&cn; float* hnp = (float*)&hn;
#pragma unroll
        for (int j = 0; j < 4; j++) {
            float cc = sigm(fv[j]) * cp[j] + sigm(iv[j]) * tanhf(gg[j]);
            cnp[j] = cc;
            hnp[j] = sigm(ov[j]) * tanhf(cc);
        }
    }
    ((float4*)g_c)[gid] = cn;
    ((float4*)g_h)[gid] = hn;
    if (store_enc)
        ((float4*)g_enc_outs)[((b * LL + t) * DH + d) >> 2] = hn;
}

// merge 125 tile stats for row b (call with all 256 threads; SM scratch).
// Writes g_lse[b][lse_t]. Returns argmax token via *tok_out (valid in all
// threads). First-max tie-break preserved: tiles ascend in column ranges.
__device__ __forceinline__ int merge_row_stats(int b, int lse_t, char* SM)
{
    int tid = threadIdx.x;
    float* mm = (float*)SM;            // 128 floats
    float* ms = mm + 128;              // 128 floats
    int*   mi = (int*)(ms + 128);      // 128 ints
    float v = -3.4e38f; int ii = 0x7fffffff;
    if (tid < NTILES_OP) { v = g_pm[b][tid]; ii = g_pi[b][tid]; }
    if (tid < 128) { mm[tid] = v; mi[tid] = ii; }
    __syncthreads();
    for (int off = 64; off >= 1; off >>= 1) {
        if (tid < off) {
            float o = mm[tid + off]; int oi = mi[tid + off];
            if (o > mm[tid] || (o == mm[tid] && oi < mi[tid])) {
                mm[tid] = o; mi[tid] = oi;
            }
        }
        __syncthreads();
    }
    float M = mm[0]; int tok = mi[0];
    __syncthreads();
    float sv = 0.f;
    if (tid < NTILES_OP) sv = g_ps[b][tid] * __expf(g_pm[b][tid] - M);
    if (tid < 128) ms[tid] = sv;
    __syncthreads();
    for (int off = 64; off >= 1; off >>= 1) {
        if (tid < off) ms[tid] += ms[tid + off];
        __syncthreads();
    }
    if (tid == 0) g_lse[b][lse_t] = M + logf(ms[0]);
    __syncthreads();
    return tok;
}

// ---------------- THE persistent kernel ------------------------------------
__global__ __launch_bounds__(256, 1) void k_persist(
    const float* __restrict__ enc_wh,
    const float* __restrict__ dec_embed, const float* __restrict__ attn_w,
    const float* __restrict__ attn_b,
    const float* __restrict__ comb_w, const float* __restrict__ comb_b,
    const float* __restrict__ dec_wx, const float* __restrict__ dec_wh,
    const float* __restrict__ dec_b,
    const float* __restrict__ out_w, const float* __restrict__ out_b,
    float* __restrict__ out)
{
    __shared__ __align__(16) char SM[41984];
    int bx = blockIdx.x, tid = threadIdx.x;
    int nb = gridDim.x;
    int nthr = nb * 256;
    int gid0 = bx * 256 + tid;

    // ---- init h=c=0 ----
    for (int u = gid0; u < BB * DH / 4; u += nthr) {
        ((float4*)g_h)[u] = make_float4(0.f, 0.f, 0.f, 0.f);
        ((float4*)g_c)[u] = make_float4(0.f, 0.f, 0.f, 0.f);
    }
    gsync();

    // ================= encoder: 64 steps =================
    for (int t = 0; t < LL; t++) {
        for (int u = bx; u < 128; u += nb) {      // 16 tiles x 8 splits (KC=128)
            int ct = u & 15, sp = u >> 4;
            int k0 = sp * 128;
            gemm256(g_h + k0, enc_wh + (size_t)k0 * G4, G4, 128,
                    g_part + (size_t)sp * BB * G4, G4, ct * 256, SM);
            __syncthreads();
        }
        gsync();
        for (int u = gid0; u < BB * DH / 4; u += nthr)
            lstm_reduce_unit(u, nullptr, 1, t, 1);
        gsync();
    }

    // ---- decoder init ----
    for (int u = gid0; u < BB * DH / 4; u += nthr) {
        ((float4*)g_h)[u] = make_float4(0.f, 0.f, 0.f, 0.f);
        ((float4*)g_c)[u] = make_float4(0.f, 0.f, 0.f, 0.f);
    }
    gsync();

    // ================= decoder: 64 steps =================
    for (int t = 0; t < LL; t++) {
        // ---- P1: per-row stats merge (t>0) + attention ----
        for (int b = bx; b < BB; b += nb) {
            int tok;
            if (t == 0) tok = 127;
            else        tok = merge_row_stats(b, t - 1, SM);

            float* se  = (float*)SM;
            float* sh  = se + DH;
            float* sc  = sh + DH;
            float* sp4 = sc + 64;
            float* red = sp4 + 256;
            for (int k = tid; k < DH; k += 256) {
                float e = dec_embed[(size_t)tok * DH + k];
                se[k] = e;
                g_e[b * DH + k] = e;
                sh[k] = g_h[b * DH + k];
            }
            __syncthreads();
            int l = tid & 63, kg = tid >> 6;
            const float* src = (kg < 2) ? (se + kg * 512) : (sh + (kg - 2) * 512);
            const float* wbase = attn_w + (size_t)(kg * 512) * LL + l;
            float p0 = 0.f, p1 = 0.f, p2 = 0.f, p3 = 0.f;
            float p4 = 0.f, p5 = 0.f, p6 = 0.f, p7 = 0.f;
#pragma unroll 2
            for (int kk = 0; kk < 512; kk += 8) {
                p0 += src[kk + 0] * wbase[(size_t)(kk + 0) * LL];
                p1 += src[kk + 1] * wbase[(size_t)(kk + 1) * LL];
                p2 += src[kk + 2] * wbase[(size_t)(kk + 2) * LL];
                p3 += src[kk + 3] * wbase[(size_t)(kk + 3) * LL];
                p4 += src[kk + 4] * wbase[(size_t)(kk + 4) * LL];
                p5 += src[kk + 5] * wbase[(size_t)(kk + 5) * LL];
                p6 += src[kk + 6] * wbase[(size_t)(kk + 6) * LL];
                p7 += src[kk + 7] * wbase[(size_t)(kk + 7) * LL];
            }
            sp4[kg * 64 + l] = ((p0 + p1) + (p2 + p3)) + ((p4 + p5) + (p6 + p7));
            __syncthreads();
            if (tid < 64)
                sc[tid] = sp4[tid] + sp4[64 + tid] + sp4[128 + tid] + sp4[192 + tid]
                        + attn_b[tid];
            __syncthreads();
            if (tid < 64) red[tid] = sc[tid];
            __syncthreads();
            for (int off = 32; off >= 1; off >>= 1) {
                if (tid < off) red[tid] = fmaxf(red[tid], red[tid + off]);
                __syncthreads();
            }
            float mx = red[0];
            __syncthreads();
            if (tid < 64) { float e = expf(sc[tid] - mx); sc[tid] = e; red[tid] = e; }
            __syncthreads();
            for (int off = 32; off >= 1; off >>= 1) {
                if (tid < off) red[tid] += red[tid + off];
                __syncthreads();
            }
            float inv = 1.f / red[0];
            __syncthreads();
            if (tid < 64) sc[tid] *= inv;
            __syncthreads();
            float4 acc4 = make_float4(0.f, 0.f, 0.f, 0.f);
            const float4* eob = (const float4*)(g_enc_outs + (size_t)b * LL * DH);
#pragma unroll 4
            for (int l2 = 0; l2 < LL; l2++) {
                float a = sc[l2];
                float4 e4 = eob[l2 * 256 + tid];
                acc4.x += a * e4.x; acc4.y += a * e4.y;
                acc4.z += a * e4.z; acc4.w += a * e4.w;
            }
            ((float4*)(g_ctx + b * DH))[tid] = acc4;
            __syncthreads();
        }
        gsync();

        // ---- P2: comb gemm (16 tiles x 8 splits, KC=256) -> g_part2 ----
        for (int u = bx; u < 128; u += nb) {
            int ct = u & 15, sp = u >> 4;
            int k0 = sp * 256;
            const float* Ab = (k0 < DH) ? (g_e + k0) : (g_ctx + k0 - DH);
            gemm64(Ab, comb_w + (size_t)k0 * DH, DH, 256,
                   g_part2 + (size_t)sp * BB * DH, DH, ct * 64, SM);
            __syncthreads();
        }
        gsync();

        // ---- P4: gates gemm (16 tiles x 8 splits over K=2048, KC=256);
        //          comb reduce+relu fused into the A-loader for k0 < DH ----
        for (int u = bx; u < 128; u += nb) {
            int ct = u & 15, sp = u >> 4;
            int k0 = sp * 256;
            if (k0 < DH) {
                gemm256_comb(k0, comb_b, dec_wx + (size_t)k0 * G4, G4, 256,
                             g_part + (size_t)sp * BB * G4, G4, ct * 256, SM);
            } else {
                gemm256(g_h + (k0 - DH), dec_wh + (size_t)(k0 - DH) * G4, G4, 256,
                        g_part + (size_t)sp * BB * G4, G4, ct * 256, SM);
            }
            __syncthreads();
        }
        gsync();

        // ---- P5: LSTM reduce ----
        for (int u = gid0; u < BB * DH / 4; u += nthr)
            lstm_reduce_unit(u, dec_b, 0, t, 0);
        gsync();

        // ---- P6: output projection + fused per-tile softmax stats ----
        for (int u = bx; u < NTILES_OP; u += nb) {
            outproj256(g_h, out_w, VV, DH, out_b, out, t, u, u * 256, SM);
            __syncthreads();
        }
        gsync();
    }

    // ================= epilogue =================
    // merge stats for the final step (t = 63)
    for (int b = bx; b < BB; b += nb)
        (void)merge_row_stats(b, LL - 1, SM);
    gsync();

    // subtract lse from all logits: out[b][t][:] -= lse[b][t]
    {
        const int TOT4 = BB * LL * (VV / 4);
        const float* lsef = &g_lse[0][0];
        float4* out4 = (float4*)out;
        for (int i = gid0; i < TOT4; i += nthr) {
            int r = i / (VV / 4);
            float l = lsef[r];
            float4 v = out4[i];
            v.x -= l; v.y -= l; v.z -= l; v.w -= l;
            out4[i] = v;
        }
    }
}

// ---------------- host launcher --------------------------------------------
extern "C" void kernel_launch(void* const* d_in, const int* in_sizes, int n_in,
                              void* d_out, int out_size)
{
    (void)in_sizes; (void)n_in; (void)out_size;
    const int*   x         = (const int*)  d_in[0];
    const float* enc_embed = (const float*)d_in[1];
    const float* enc_wx    = (const float*)d_in[2];
    const float* enc_wh    = (const float*)d_in[3];
    const float* enc_b     = (const float*)d_in[4];
    const float* dec_embed = (const float*)d_in[5];
    const float* attn_w    = (const float*)d_in[6];
    const float* attn_b    = (const float*)d_in[7];
    const float* comb_w    = (const float*)d_in[8];
    const float* comb_b    = (const float*)d_in[9];
    const float* dec_wx    = (const float*)d_in[10];
    const float* dec_wh    = (const float*)d_in[11];
    const float* dec_b     = (const float*)d_in[12];
    const float* out_w     = (const float*)d_in[13];
    const float* out_b     = (const float*)d_in[14];
    float* out = (float*)d_out;

    int dev = 0, nsm = MAXBLK;
    cudaGetDevice(&dev);
    cudaDeviceGetAttribute(&nsm, cudaDevAttrMultiProcessorCount, dev);
    int nblk = nsm < MAXBLK ? nsm : MAXBLK;

    k_enc_pre<<<dim3(32, 1, 64), 256>>>(x, enc_embed, enc_wx, enc_b);
    k_persist<<<nblk, 256>>>(enc_wh, dec_embed, attn_w, attn_b,
                             comb_w, comb_b, dec_wx, dec_wh, dec_b,
                             out_w, out_b, out);
}